// round 6
// baseline (speedup 1.0000x reference)
#include <cuda_runtime.h>
#include <math.h>

#define DMODEL 768
#define HEADS 12
#define DHEAD 64
#define NLAYER 2
#define RRAND 3
#define BATCH 2
#define SEQ 4096
#define NBLK 64              // SEQ / 64
#define TOK (BATCH*SEQ)      // 8192
#define DFF (4*DMODEL)       // 3072

// ---------------- scratch (device globals; no runtime allocation) ----------------
__device__ float g_x [TOK*DMODEL];
__device__ float g_q [TOK*DMODEL];
__device__ float g_k [TOK*DMODEL];
__device__ float g_v [TOK*DMODEL];
__device__ float g_ao[TOK*DMODEL];
__device__ float g_t [TOK*DMODEL];
__device__ float g_h [TOK*DFF];
__device__ float g_fs[BATCH*HEADS*2*64*SEQ];   // full-attn scores (also reused as pool partials)

// ---------------- reductions ----------------
__device__ __forceinline__ float blockSum(float v, float* red) {
    __syncthreads();
    #pragma unroll
    for (int o = 16; o; o >>= 1) v += __shfl_down_sync(0xffffffffu, v, o);
    if ((threadIdx.x & 31) == 0) red[threadIdx.x >> 5] = v;
    __syncthreads();
    float r = (threadIdx.x < 8) ? red[threadIdx.x] : 0.f;
    if (threadIdx.x < 32) {
        #pragma unroll
        for (int o = 16; o; o >>= 1) r += __shfl_down_sync(0xffffffffu, r, o);
    }
    if (threadIdx.x == 0) red[0] = r;
    __syncthreads();
    return red[0];
}

__device__ __forceinline__ float blockMax(float v, float* red) {
    __syncthreads();
    #pragma unroll
    for (int o = 16; o; o >>= 1) v = fmaxf(v, __shfl_down_sync(0xffffffffu, v, o));
    if ((threadIdx.x & 31) == 0) red[threadIdx.x >> 5] = v;
    __syncthreads();
    float r = (threadIdx.x < 8) ? red[threadIdx.x] : -1e30f;
    if (threadIdx.x < 32) {
        #pragma unroll
        for (int o = 16; o; o >>= 1) r = fmaxf(r, __shfl_down_sync(0xffffffffu, r, o));
    }
    if (threadIdx.x == 0) red[0] = r;
    __syncthreads();
    return red[0];
}

// ---------------- embedding + layernorm ----------------
__global__ __launch_bounds__(256) void embed_ln(
    const int* __restrict__ ids, const float* __restrict__ etok,
    const float* __restrict__ epos, const float* __restrict__ g,
    const float* __restrict__ bi, float* __restrict__ x)
{
    __shared__ float red[8];
    int t = blockIdx.x;
    int s = t & (SEQ - 1);
    int tid = threadIdx.x;
    int id = ids[t];
    float e[3]; float sum = 0.f;
    #pragma unroll
    for (int i = 0; i < 3; i++) {
        int d = tid + i*256;
        e[i] = etok[(size_t)id*DMODEL + d] + epos[(size_t)s*DMODEL + d];
        sum += e[i];
    }
    float mean = blockSum(sum, red) * (1.f/DMODEL);
    float vs = 0.f;
    #pragma unroll
    for (int i = 0; i < 3; i++) { float df = e[i]-mean; vs += df*df; }
    float var = blockSum(vs, red) * (1.f/DMODEL);
    float inv = rsqrtf(var + 1e-12f);
    #pragma unroll
    for (int i = 0; i < 3; i++) {
        int d = tid + i*256;
        x[(size_t)t*DMODEL + d] = (e[i]-mean)*inv*g[d] + bi[d];
    }
}

// ---------------- residual add + layernorm (in-place on x) ----------------
__global__ __launch_bounds__(256) void add_ln(
    float* __restrict__ x, const float* __restrict__ y,
    const float* __restrict__ g, const float* __restrict__ bi)
{
    __shared__ float red[8];
    int t = blockIdx.x;
    int tid = threadIdx.x;
    float e[3]; float sum = 0.f;
    #pragma unroll
    for (int i = 0; i < 3; i++) {
        int d = tid + i*256;
        e[i] = x[(size_t)t*DMODEL + d] + y[(size_t)t*DMODEL + d];
        sum += e[i];
    }
    float mean = blockSum(sum, red) * (1.f/DMODEL);
    float vs = 0.f;
    #pragma unroll
    for (int i = 0; i < 3; i++) { float df = e[i]-mean; vs += df*df; }
    float var = blockSum(vs, red) * (1.f/DMODEL);
    float inv = rsqrtf(var + 1e-12f);
    #pragma unroll
    for (int i = 0; i < 3; i++) {
        int d = tid + i*256;
        x[(size_t)t*DMODEL + d] = (e[i]-mean)*inv*g[d] + bi[d];
    }
}

// ---------------- tiled SGEMM: C[M,N] = A[M,K] @ B[K,N] + bias, opt GELU ----------------
// BM=BN=128, BK=16, 256 threads, 8x8 per-thread tile. M%128==0, N%128==0, K%16==0.
__global__ __launch_bounds__(256) void sgemm(
    const float* __restrict__ A, const float* __restrict__ B,
    const float* __restrict__ bias, float* __restrict__ C,
    int M, int N, int K, int act)
{
    __shared__ float As[16][132];
    __shared__ float Bs[16][132];
    const int tid = threadIdx.x;
    const int tr = tid >> 4, tc = tid & 15;
    const int bm = blockIdx.y << 7;
    const int bn = blockIdx.x << 7;
    float acc[8][8] = {};
    const int f0 = tid * 2;
    for (int k0 = 0; k0 < K; k0 += 16) {
        #pragma unroll
        for (int i = 0; i < 2; i++) {
            int f = f0 + i;
            int ar = f >> 2, ac = (f & 3) << 2;
            float4 av = *(const float4*)(A + (size_t)(bm+ar)*K + k0 + ac);
            As[ac+0][ar] = av.x; As[ac+1][ar] = av.y;
            As[ac+2][ar] = av.z; As[ac+3][ar] = av.w;
            int br = f >> 5, bc = (f & 31) << 2;
            *(float4*)&Bs[br][bc] = *(const float4*)(B + (size_t)(k0+br)*N + bn + bc);
        }
        __syncthreads();
        #pragma unroll
        for (int kk = 0; kk < 16; kk++) {
            float a[8], bb[8];
            *(float4*)(a)    = *(float4*)&As[kk][tr*8];
            *(float4*)(a+4)  = *(float4*)&As[kk][tr*8+4];
            *(float4*)(bb)   = *(float4*)&Bs[kk][tc*8];
            *(float4*)(bb+4) = *(float4*)&Bs[kk][tc*8+4];
            #pragma unroll
            for (int i = 0; i < 8; i++)
                #pragma unroll
                for (int j = 0; j < 8; j++)
                    acc[i][j] = fmaf(a[i], bb[j], acc[i][j]);
        }
        __syncthreads();
    }
    #pragma unroll
    for (int i = 0; i < 8; i++) {
        int row = bm + tr*8 + i;
        #pragma unroll
        for (int j = 0; j < 8; j++) {
            int col = bn + tc*8 + j;
            float u = acc[i][j] + bias[col];
            if (act) {
                u = 0.5f*u*(1.f + tanhf(0.7978845608028654f*(u + 0.044715f*u*u*u)));
            }
            C[(size_t)row*N + col] = u;
        }
    }
}

// ---------------- sparse block attention (query blocks 1..62) ----------------
// grid (62, H, B). One CTA handles 64 queries x 512 gathered keys, 256 threads.
// dyn smem: Sc[64*512] + Qt[64*68] + KV[64*68]
#define SPARSE_SMEM ((64*512 + 64*68 + 64*68) * 4)
__global__ __launch_bounds__(256) void sparse_attn(
    const float* __restrict__ q, const float* __restrict__ k,
    const float* __restrict__ v, const int* __restrict__ rnd,
    float* __restrict__ out)
{
    extern __shared__ float sm[];
    float* Sc = sm;                    // [64][512]
    float* Qt = sm + 64*512;           // [d][qr] stride 68
    float* KV = Qt + 64*68;            // Kt: [d][kc] / Vs: [kc][dh], stride 68
    const int qb = blockIdx.x + 1;     // 1..62
    const int h = blockIdx.y, b = blockIdx.z;
    const int tid = threadIdx.x;
    const int tr = tid >> 4, tc = tid & 15;

    int idx[8];
    idx[0] = 0; idx[1] = qb-1; idx[2] = qb; idx[3] = qb+1; idx[4] = NBLK-1;
    #pragma unroll
    for (int j = 0; j < RRAND; j++)
        idx[5+j] = rnd[((size_t)h*NBLK + qb)*RRAND + j];

    const float scale = 0.125f;
    const float* qbase = q + ((size_t)(b*SEQ + qb*64))*DMODEL + h*DHEAD;
    for (int e = tid; e < 64*64; e += 256) {
        int r = e >> 6, d = e & 63;
        Qt[d*68 + r] = qbase[(size_t)r*DMODEL + d];
    }
    // ---- scores ----
    for (int kb = 0; kb < 8; kb++) {
        const float* kbase = k + ((size_t)(b*SEQ + idx[kb]*64))*DMODEL + h*DHEAD;
        __syncthreads();
        for (int e = tid; e < 64*64; e += 256) {
            int r = e >> 6, d = e & 63;
            KV[d*68 + r] = kbase[(size_t)r*DMODEL + d];
        }
        __syncthreads();
        float acc[4][4] = {};
        #pragma unroll 8
        for (int d = 0; d < 64; d++) {
            float a[4], bb[4];
            #pragma unroll
            for (int i = 0; i < 4; i++) a[i] = Qt[d*68 + tr*4 + i];
            #pragma unroll
            for (int j = 0; j < 4; j++) bb[j] = KV[d*68 + tc*4 + j];
            #pragma unroll
            for (int i = 0; i < 4; i++)
                #pragma unroll
                for (int j = 0; j < 4; j++)
                    acc[i][j] = fmaf(a[i], bb[j], acc[i][j]);
        }
        #pragma unroll
        for (int i = 0; i < 4; i++)
            #pragma unroll
            for (int j = 0; j < 4; j++)
                Sc[(tr*4+i)*512 + kb*64 + tc*4 + j] = acc[i][j] * scale;
    }
    __syncthreads();
    // ---- softmax: 4 lanes per row ----
    {
        int row = tid >> 2, sub = tid & 3;
        float m = -1e30f;
        for (int c = sub; c < 512; c += 4) m = fmaxf(m, Sc[row*512 + c]);
        m = fmaxf(m, __shfl_xor_sync(0xffffffffu, m, 1));
        m = fmaxf(m, __shfl_xor_sync(0xffffffffu, m, 2));
        float s = 0.f;
        for (int c = sub; c < 512; c += 4) {
            float ev = __expf(Sc[row*512 + c] - m);
            Sc[row*512 + c] = ev; s += ev;
        }
        s += __shfl_xor_sync(0xffffffffu, s, 1);
        s += __shfl_xor_sync(0xffffffffu, s, 2);
        float inv = 1.f / s;
        for (int c = sub; c < 512; c += 4) Sc[row*512 + c] *= inv;
    }
    // ---- P @ V ----
    float acc[4][4] = {};
    for (int kb = 0; kb < 8; kb++) {
        const float* vbase = v + ((size_t)(b*SEQ + idx[kb]*64))*DMODEL + h*DHEAD;
        __syncthreads();
        for (int e = tid; e < 64*64; e += 256) {
            int r = e >> 6, d = e & 63;
            KV[r*68 + d] = vbase[(size_t)r*DMODEL + d];
        }
        __syncthreads();
        #pragma unroll 8
        for (int kk = 0; kk < 64; kk++) {
            float p[4], vv[4];
            #pragma unroll
            for (int i = 0; i < 4; i++) p[i] = Sc[(tr*4+i)*512 + kb*64 + kk];
            #pragma unroll
            for (int j = 0; j < 4; j++) vv[j] = KV[kk*68 + tc*4 + j];
            #pragma unroll
            for (int i = 0; i < 4; i++)
                #pragma unroll
                for (int j = 0; j < 4; j++)
                    acc[i][j] = fmaf(p[i], vv[j], acc[i][j]);
        }
    }
    float* obase = out + ((size_t)(b*SEQ + qb*64))*DMODEL + h*DHEAD;
    #pragma unroll
    for (int i = 0; i < 4; i++)
        #pragma unroll
        for (int j = 0; j < 4; j++)
            obase[(size_t)(tr*4+i)*DMODEL + tc*4 + j] = acc[i][j];
}

// ---------------- full attention for query blocks 0 and 63 ----------------
// scores: grid (64 kblocks, 2 rbi, B*H)
__global__ __launch_bounds__(256) void fa_scores(
    const float* __restrict__ q, const float* __restrict__ k, float* __restrict__ fs)
{
    __shared__ float Qt[64*68];
    __shared__ float Kt[64*68];
    int kb = blockIdx.x, rbi = blockIdx.y, bh = blockIdx.z;
    int b = bh / HEADS, h = bh % HEADS;
    int qb = rbi ? (NBLK-1) : 0;
    int tid = threadIdx.x;
    const float* qbase = q + ((size_t)(b*SEQ + qb*64))*DMODEL + h*DHEAD;
    const float* kbase = k + ((size_t)(b*SEQ + kb*64))*DMODEL + h*DHEAD;
    for (int e = tid; e < 64*64; e += 256) {
        int r = e >> 6, d = e & 63;
        Qt[d*68 + r] = qbase[(size_t)r*DMODEL + d];
        Kt[d*68 + r] = kbase[(size_t)r*DMODEL + d];
    }
    __syncthreads();
    int tr = tid >> 4, tc = tid & 15;
    float acc[4][4] = {};
    #pragma unroll 8
    for (int d = 0; d < 64; d++) {
        float a[4], bb[4];
        #pragma unroll
        for (int i = 0; i < 4; i++) a[i] = Qt[d*68 + tr*4 + i];
        #pragma unroll
        for (int j = 0; j < 4; j++) bb[j] = Kt[d*68 + tc*4 + j];
        #pragma unroll
        for (int i = 0; i < 4; i++)
            #pragma unroll
            for (int j = 0; j < 4; j++)
                acc[i][j] = fmaf(a[i], bb[j], acc[i][j]);
    }
    const float scale = 0.125f;
    float* orow = fs + ((size_t)(bh*2 + rbi)*64)*SEQ + kb*64;
    #pragma unroll
    for (int i = 0; i < 4; i++)
        #pragma unroll
        for (int j = 0; j < 4; j++)
            orow[(size_t)(tr*4+i)*SEQ + tc*4 + j] = acc[i][j] * scale;
}

__global__ __launch_bounds__(256) void fa_softmax(float* __restrict__ fs)
{
    __shared__ float red[8];
    float* rowp = fs + (size_t)blockIdx.x * SEQ;
    int tid = threadIdx.x;
    float m = -1e30f;
    for (int c = tid; c < SEQ; c += 256) m = fmaxf(m, rowp[c]);
    m = blockMax(m, red);
    float s = 0.f;
    for (int c = tid; c < SEQ; c += 256) {
        float ev = __expf(rowp[c] - m);
        rowp[c] = ev; s += ev;
    }
    s = blockSum(s, red);
    float inv = 1.f / s;
    for (int c = tid; c < SEQ; c += 256) rowp[c] *= inv;
}

// P@V for full rows: grid (2 rbi, B*H)
__global__ __launch_bounds__(256) void fa_pv(
    const float* __restrict__ fs, const float* __restrict__ v, float* __restrict__ out)
{
    __shared__ float Ps[64*68];
    __shared__ float Vs[64*68];
    int rbi = blockIdx.x, bh = blockIdx.y;
    int b = bh / HEADS, h = bh % HEADS;
    int qb = rbi ? (NBLK-1) : 0;
    int tid = threadIdx.x;
    int tr = tid >> 4, tc = tid & 15;
    float acc[4][4] = {};
    const float* prow = fs + ((size_t)(bh*2 + rbi)*64)*SEQ;
    for (int kb = 0; kb < NBLK; kb++) {
        const float* vbase = v + ((size_t)(b*SEQ + kb*64))*DMODEL + h*DHEAD;
        __syncthreads();
        for (int e = tid; e < 64*64; e += 256) {
            int r = e >> 6, c = e & 63;
            Ps[r*68 + c] = prow[(size_t)r*SEQ + kb*64 + c];
            Vs[r*68 + c] = vbase[(size_t)r*DMODEL + c];
        }
        __syncthreads();
        #pragma unroll 8
        for (int kk = 0; kk < 64; kk++) {
            float p[4], vv[4];
            #pragma unroll
            for (int i = 0; i < 4; i++) p[i] = Ps[(tr*4+i)*68 + kk];
            #pragma unroll
            for (int j = 0; j < 4; j++) vv[j] = Vs[kk*68 + tc*4 + j];
            #pragma unroll
            for (int i = 0; i < 4; i++)
                #pragma unroll
                for (int j = 0; j < 4; j++)
                    acc[i][j] = fmaf(p[i], vv[j], acc[i][j]);
        }
    }
    float* obase = out + ((size_t)(b*SEQ + qb*64))*DMODEL + h*DHEAD;
    #pragma unroll
    for (int i = 0; i < 4; i++)
        #pragma unroll
        for (int j = 0; j < 4; j++)
            obase[(size_t)(tr*4+i)*DMODEL + tc*4 + j] = acc[i][j];
}

// ---------------- mean pool + fc ----------------
__global__ __launch_bounds__(256) void pool1(const float* __restrict__ x, float* __restrict__ part)
{
    int c = blockIdx.x, b = blockIdx.y;
    int tid = threadIdx.x;
    #pragma unroll
    for (int i = 0; i < 3; i++) {
        int d = tid + i*256;
        const float* base = x + ((size_t)(b*SEQ + c*64))*DMODEL + d;
        float s = 0.f;
        #pragma unroll 8
        for (int t = 0; t < 64; t++) s += base[(size_t)t*DMODEL];
        part[((size_t)(b*64 + c))*DMODEL + d] = s;
    }
}

__global__ __launch_bounds__(256) void pool2(
    const float* __restrict__ part, const float* __restrict__ fcw,
    const float* __restrict__ fcb, float* __restrict__ out)
{
    __shared__ float red[8];
    int b = blockIdx.x, tid = threadIdx.x;
    float accv = 0.f;
    #pragma unroll
    for (int i = 0; i < 3; i++) {
        int d = tid + i*256;
        float s = 0.f;
        for (int c = 0; c < 64; c++) s += part[((size_t)(b*64 + c))*DMODEL + d];
        accv += (s * (1.f/SEQ)) * fcw[d];
    }
    float tot = blockSum(accv, red);
    if (tid == 0) out[b] = tot + fcb[0];
}

// ---------------- launch ----------------
extern "C" void kernel_launch(void* const* d_in, const int* in_sizes, int n_in,
                              void* d_out, int out_size)
{
    const int*   ids   = (const int*)  d_in[0];
    const int*   rnd   = (const int*)  d_in[1];
    const float* etok  = (const float*)d_in[2];
    const float* epos  = (const float*)d_in[3];
    const float* lng   = (const float*)d_in[4];
    const float* lnb   = (const float*)d_in[5];
    const float* Wq    = (const float*)d_in[6];
    const float* bq    = (const float*)d_in[7];
    const float* Wk    = (const float*)d_in[8];
    const float* bk    = (const float*)d_in[9];
    const float* Wv    = (const float*)d_in[10];
    const float* bv    = (const float*)d_in[11];
    const float* Wo    = (const float*)d_in[12];
    const float* bo    = (const float*)d_in[13];
    const float* ln1g  = (const float*)d_in[14];
    const float* ln1b  = (const float*)d_in[15];
    const float* W1    = (const float*)d_in[16];
    const float* b1    = (const float*)d_in[17];
    const float* W2    = (const float*)d_in[18];
    const float* b2    = (const float*)d_in[19];
    const float* ln2g  = (const float*)d_in[20];
    const float* ln2b  = (const float*)d_in[21];
    const float* fcw   = (const float*)d_in[22];
    const float* fcb   = (const float*)d_in[23];
    float* out = (float*)d_out;

    float *x, *q, *k, *v, *ao, *t, *h, *fs;
    cudaGetSymbolAddress((void**)&x,  g_x);
    cudaGetSymbolAddress((void**)&q,  g_q);
    cudaGetSymbolAddress((void**)&k,  g_k);
    cudaGetSymbolAddress((void**)&v,  g_v);
    cudaGetSymbolAddress((void**)&ao, g_ao);
    cudaGetSymbolAddress((void**)&t,  g_t);
    cudaGetSymbolAddress((void**)&h,  g_h);
    cudaGetSymbolAddress((void**)&fs, g_fs);

    cudaFuncSetAttribute(sparse_attn, cudaFuncAttributeMaxDynamicSharedMemorySize, SPARSE_SMEM);

    embed_ln<<<TOK, 256>>>(ids, etok, epos, lng, lnb, x);

    for (int l = 0; l < NLAYER; l++) {
        const float* Wql = Wq + (size_t)l*DMODEL*DMODEL;
        const float* Wkl = Wk + (size_t)l*DMODEL*DMODEL;
        const float* Wvl = Wv + (size_t)l*DMODEL*DMODEL;
        const float* Wol = Wo + (size_t)l*DMODEL*DMODEL;
        const float* W1l = W1 + (size_t)l*DMODEL*DFF;
        const float* W2l = W2 + (size_t)l*DFF*DMODEL;

        dim3 gQKV(DMODEL/128, TOK/128);
        sgemm<<<gQKV, 256>>>(x, Wql, bq + l*DMODEL, q, TOK, DMODEL, DMODEL, 0);
        sgemm<<<gQKV, 256>>>(x, Wkl, bk + l*DMODEL, k, TOK, DMODEL, DMODEL, 0);
        sgemm<<<gQKV, 256>>>(x, Wvl, bv + l*DMODEL, v, TOK, DMODEL, DMODEL, 0);

        sparse_attn<<<dim3(NBLK-2, HEADS, BATCH), 256, SPARSE_SMEM>>>(q, k, v, rnd, ao);
        fa_scores<<<dim3(NBLK, 2, BATCH*HEADS), 256>>>(q, k, fs);
        fa_softmax<<<BATCH*HEADS*2*64, 256>>>(fs);
        fa_pv<<<dim3(2, BATCH*HEADS), 256>>>(fs, v, ao);

        sgemm<<<gQKV, 256>>>(ao, Wol, bo + l*DMODEL, t, TOK, DMODEL, DMODEL, 0);
        add_ln<<<TOK, 256>>>(x, t, ln1g + l*DMODEL, ln1b + l*DMODEL);

        sgemm<<<dim3(DFF/128, TOK/128), 256>>>(x, W1l, b1 + l*DFF, h, TOK, DFF, DMODEL, 1);
        sgemm<<<dim3(DMODEL/128, TOK/128), 256>>>(h, W2l, b2 + l*DMODEL, t, TOK, DMODEL, DFF, 0);
        add_ln<<<TOK, 256>>>(x, t, ln2g + l*DMODEL, ln2b + l*DMODEL);
    }

    pool1<<<dim3(64, BATCH), 256>>>(x, fs);
    pool2<<<BATCH, 256>>>(fs, fcw, fcb, out);
}

// round 7
// speedup vs baseline: 2.1561x; 2.1561x over previous
#include <cuda_runtime.h>
#include <math.h>
#include <stdint.h>

#define DMODEL 768
#define HEADS 12
#define DHEAD 64
#define NLAYER 2
#define RRAND 3
#define BATCH 2
#define SEQ 4096
#define NBLK 64              // SEQ / 64
#define TOK (BATCH*SEQ)      // 8192
#define DFF (4*DMODEL)       // 3072

// ---------------- scratch (device globals; no runtime allocation) ----------------
__device__ float g_x [TOK*DMODEL];
__device__ float g_q [TOK*DMODEL];
__device__ float g_k [TOK*DMODEL];
__device__ float g_v [TOK*DMODEL];
__device__ float g_ao[TOK*DMODEL];
__device__ float g_t [TOK*DMODEL];
__device__ float g_h [TOK*DFF];
__device__ float g_fs[BATCH*HEADS*2*64*SEQ];   // full-attn scores (also reused as pool partials)

// ---------------- reductions ----------------
__device__ __forceinline__ float blockSum(float v, float* red) {
    __syncthreads();
    #pragma unroll
    for (int o = 16; o; o >>= 1) v += __shfl_down_sync(0xffffffffu, v, o);
    if ((threadIdx.x & 31) == 0) red[threadIdx.x >> 5] = v;
    __syncthreads();
    float r = (threadIdx.x < 8) ? red[threadIdx.x] : 0.f;
    if (threadIdx.x < 32) {
        #pragma unroll
        for (int o = 16; o; o >>= 1) r += __shfl_down_sync(0xffffffffu, r, o);
    }
    if (threadIdx.x == 0) red[0] = r;
    __syncthreads();
    return red[0];
}

__device__ __forceinline__ float blockMax(float v, float* red) {
    __syncthreads();
    #pragma unroll
    for (int o = 16; o; o >>= 1) v = fmaxf(v, __shfl_down_sync(0xffffffffu, v, o));
    if ((threadIdx.x & 31) == 0) red[threadIdx.x >> 5] = v;
    __syncthreads();
    float r = (threadIdx.x < 8) ? red[threadIdx.x] : -1e30f;
    if (threadIdx.x < 32) {
        #pragma unroll
        for (int o = 16; o; o >>= 1) r = fmaxf(r, __shfl_down_sync(0xffffffffu, r, o));
    }
    if (threadIdx.x == 0) red[0] = r;
    __syncthreads();
    return red[0];
}

// ---------------- embedding + layernorm ----------------
__global__ __launch_bounds__(256) void embed_ln(
    const int* __restrict__ ids, const float* __restrict__ etok,
    const float* __restrict__ epos, const float* __restrict__ g,
    const float* __restrict__ bi, float* __restrict__ x)
{
    __shared__ float red[8];
    int t = blockIdx.x;
    int s = t & (SEQ - 1);
    int tid = threadIdx.x;
    int id = ids[t];
    float e[3]; float sum = 0.f;
    #pragma unroll
    for (int i = 0; i < 3; i++) {
        int d = tid + i*256;
        e[i] = etok[(size_t)id*DMODEL + d] + epos[(size_t)s*DMODEL + d];
        sum += e[i];
    }
    float mean = blockSum(sum, red) * (1.f/DMODEL);
    float vs = 0.f;
    #pragma unroll
    for (int i = 0; i < 3; i++) { float df = e[i]-mean; vs += df*df; }
    float var = blockSum(vs, red) * (1.f/DMODEL);
    float inv = rsqrtf(var + 1e-12f);
    #pragma unroll
    for (int i = 0; i < 3; i++) {
        int d = tid + i*256;
        x[(size_t)t*DMODEL + d] = (e[i]-mean)*inv*g[d] + bi[d];
    }
}

// ---------------- residual add + layernorm (in-place on x) ----------------
__global__ __launch_bounds__(256) void add_ln(
    float* __restrict__ x, const float* __restrict__ y,
    const float* __restrict__ g, const float* __restrict__ bi)
{
    __shared__ float red[8];
    int t = blockIdx.x;
    int tid = threadIdx.x;
    float e[3]; float sum = 0.f;
    #pragma unroll
    for (int i = 0; i < 3; i++) {
        int d = tid + i*256;
        e[i] = x[(size_t)t*DMODEL + d] + y[(size_t)t*DMODEL + d];
        sum += e[i];
    }
    float mean = blockSum(sum, red) * (1.f/DMODEL);
    float vs = 0.f;
    #pragma unroll
    for (int i = 0; i < 3; i++) { float df = e[i]-mean; vs += df*df; }
    float var = blockSum(vs, red) * (1.f/DMODEL);
    float inv = rsqrtf(var + 1e-12f);
    #pragma unroll
    for (int i = 0; i < 3; i++) {
        int d = tid + i*256;
        x[(size_t)t*DMODEL + d] = (e[i]-mean)*inv*g[d] + bi[d];
    }
}

// ---------------- helpers for tf32 tensor-core GEMM ----------------
__device__ __forceinline__ void cpa16(void* dst, const void* src) {
    uint32_t d = (uint32_t)__cvta_generic_to_shared(dst);
    asm volatile("cp.async.cg.shared.global [%0], [%1], 16;" :: "r"(d), "l"(src));
}
__device__ __forceinline__ uint32_t f2tf(float x) {
    uint32_t u;
    asm("cvt.rna.tf32.f32 %0, %1;" : "=r"(u) : "f"(x));
    return u;
}
__device__ __forceinline__ void mma_tf32(float* c, const uint32_t* a, const uint32_t* b) {
    asm volatile(
        "mma.sync.aligned.m16n8k8.row.col.f32.tf32.tf32.f32 "
        "{%0,%1,%2,%3},{%4,%5,%6,%7},{%8,%9},{%0,%1,%2,%3};"
        : "+f"(c[0]), "+f"(c[1]), "+f"(c[2]), "+f"(c[3])
        : "r"(a[0]), "r"(a[1]), "r"(a[2]), "r"(a[3]), "r"(b[0]), "r"(b[1]));
}

// ---------------- tf32 tensor-core GEMM: C[M,N] = A[M,K] @ B[K,N] + bias, opt GELU ----------
// BM=BN=128, BK=32, 256 threads. Warp grid 2(M)x4(N), warp tile 64x32 = 4x4 m16n8k8.
// A smem [stage][128][36] (m-major, pad 4), B smem [stage][32][136] (k-major, pad 8).
// M%128==0, N%128==0, K%32==0 (holds for all uses).
#define A_PAD 36
#define B_PAD 136
#define GEMM_SMEM ((2*128*A_PAD + 2*32*B_PAD) * 4)

__global__ __launch_bounds__(256, 2) void gemm_tf32(
    const float* __restrict__ A, const float* __restrict__ B,
    const float* __restrict__ bias, float* __restrict__ C,
    int M, int N, int K, int act)
{
    extern __shared__ float sm[];
    float* As = sm;                     // [2][128][A_PAD]
    float* Bs = sm + 2*128*A_PAD;       // [2][32][B_PAD]

    const int tid  = threadIdx.x;
    const int warp = tid >> 5, lane = tid & 31;
    const int g = lane >> 2, t = lane & 3;     // groupID, threadID-in-group
    const int wm = warp >> 2;                  // 0..1
    const int wn = warp & 3;                   // 0..3
    const int bm = blockIdx.y << 7;
    const int bn = blockIdx.x << 7;

    float acc[4][4][4] = {};

    // stage loader: A tile 128x32 + B tile 32x128, one commit group
    auto load_stage = [&](int stg, int k0) {
        float* Ad = As + stg*128*A_PAD;
        float* Bd = Bs + stg*32*B_PAD;
        #pragma unroll
        for (int i = 0; i < 4; i++) {
            int f = tid + i*256;
            int r = f >> 3, c = (f & 7) << 2;
            cpa16(Ad + r*A_PAD + c, A + (size_t)(bm+r)*K + k0 + c);
            int br = f >> 5, bc = (f & 31) << 2;
            cpa16(Bd + br*B_PAD + bc, B + (size_t)(k0+br)*N + bn + bc);
        }
        asm volatile("cp.async.commit_group;" ::: "memory");
    };

    load_stage(0, 0);
    int stg = 0;
    for (int k0 = 0; k0 < K; k0 += 32, stg ^= 1) {
        if (k0 + 32 < K) {
            load_stage(stg ^ 1, k0 + 32);
            asm volatile("cp.async.wait_group 1;" ::: "memory");
        } else {
            asm volatile("cp.async.wait_group 0;" ::: "memory");
        }
        __syncthreads();

        const float* Ac = As + stg*128*A_PAD;
        const float* Bc = Bs + stg*32*B_PAD;
        #pragma unroll
        for (int ks = 0; ks < 4; ks++) {
            const int kb = ks*8;
            uint32_t af[4][4], bf[4][2];
            #pragma unroll
            for (int mt = 0; mt < 4; mt++) {
                int m = wm*64 + mt*16 + g;
                af[mt][0] = f2tf(Ac[(m  )*A_PAD + kb + t    ]);
                af[mt][1] = f2tf(Ac[(m+8)*A_PAD + kb + t    ]);
                af[mt][2] = f2tf(Ac[(m  )*A_PAD + kb + t + 4]);
                af[mt][3] = f2tf(Ac[(m+8)*A_PAD + kb + t + 4]);
            }
            #pragma unroll
            for (int nt = 0; nt < 4; nt++) {
                int n = wn*32 + nt*8 + g;
                bf[nt][0] = f2tf(Bc[(kb + t    )*B_PAD + n]);
                bf[nt][1] = f2tf(Bc[(kb + t + 4)*B_PAD + n]);
            }
            #pragma unroll
            for (int mt = 0; mt < 4; mt++)
                #pragma unroll
                for (int nt = 0; nt < 4; nt++)
                    mma_tf32(acc[mt][nt], af[mt], bf[nt]);
        }
        __syncthreads();
    }

    // epilogue
    #pragma unroll
    for (int mt = 0; mt < 4; mt++) {
        #pragma unroll
        for (int nt = 0; nt < 4; nt++) {
            int row = bm + wm*64 + mt*16 + g;
            int col = bn + wn*32 + nt*8 + t*2;
            float b0 = bias[col], b1 = bias[col+1];
            #pragma unroll
            for (int h = 0; h < 2; h++) {       // h=0: rows g, h=1: rows g+8
                float u0 = acc[mt][nt][2*h+0] + b0;
                float u1 = acc[mt][nt][2*h+1] + b1;
                if (act) {
                    u0 = 0.5f*u0*(1.f + tanhf(0.7978845608028654f*(u0 + 0.044715f*u0*u0*u0)));
                    u1 = 0.5f*u1*(1.f + tanhf(0.7978845608028654f*(u1 + 0.044715f*u1*u1*u1)));
                }
                float2 p = make_float2(u0, u1);
                *(float2*)(C + (size_t)(row + 8*h)*N + col) = p;
            }
        }
    }
}

// ---------------- sparse block attention (query blocks 1..62) ----------------
// grid (62, H, B). One CTA handles 64 queries x 512 gathered keys, 256 threads.
// dyn smem: Sc[64*512] + Qt[64*68] + KV[64*68]
#define SPARSE_SMEM ((64*512 + 64*68 + 64*68) * 4)
__global__ __launch_bounds__(256) void sparse_attn(
    const float* __restrict__ q, const float* __restrict__ k,
    const float* __restrict__ v, const int* __restrict__ rnd,
    float* __restrict__ out)
{
    extern __shared__ float sm[];
    float* Sc = sm;                    // [64][512]
    float* Qt = sm + 64*512;           // [d][qr] stride 68
    float* KV = Qt + 64*68;            // Kt: [d][kc] / Vs: [kc][dh], stride 68
    const int qb = blockIdx.x + 1;     // 1..62
    const int h = blockIdx.y, b = blockIdx.z;
    const int tid = threadIdx.x;
    const int tr = tid >> 4, tc = tid & 15;

    int idx[8];
    idx[0] = 0; idx[1] = qb-1; idx[2] = qb; idx[3] = qb+1; idx[4] = NBLK-1;
    #pragma unroll
    for (int j = 0; j < RRAND; j++)
        idx[5+j] = rnd[((size_t)h*NBLK + qb)*RRAND + j];

    const float scale = 0.125f;
    const float* qbase = q + ((size_t)(b*SEQ + qb*64))*DMODEL + h*DHEAD;
    for (int e = tid; e < 64*64; e += 256) {
        int r = e >> 6, d = e & 63;
        Qt[d*68 + r] = qbase[(size_t)r*DMODEL + d];
    }
    // ---- scores ----
    for (int kb = 0; kb < 8; kb++) {
        const float* kbase = k + ((size_t)(b*SEQ + idx[kb]*64))*DMODEL + h*DHEAD;
        __syncthreads();
        for (int e = tid; e < 64*64; e += 256) {
            int r = e >> 6, d = e & 63;
            KV[d*68 + r] = kbase[(size_t)r*DMODEL + d];
        }
        __syncthreads();
        float acc[4][4] = {};
        #pragma unroll 8
        for (int d = 0; d < 64; d++) {
            float a[4], bb[4];
            #pragma unroll
            for (int i = 0; i < 4; i++) a[i] = Qt[d*68 + tr*4 + i];
            #pragma unroll
            for (int j = 0; j < 4; j++) bb[j] = KV[d*68 + tc*4 + j];
            #pragma unroll
            for (int i = 0; i < 4; i++)
                #pragma unroll
                for (int j = 0; j < 4; j++)
                    acc[i][j] = fmaf(a[i], bb[j], acc[i][j]);
        }
        #pragma unroll
        for (int i = 0; i < 4; i++)
            #pragma unroll
            for (int j = 0; j < 4; j++)
                Sc[(tr*4+i)*512 + kb*64 + tc*4 + j] = acc[i][j] * scale;
    }
    __syncthreads();
    // ---- softmax: 4 lanes per row ----
    {
        int row = tid >> 2, sub = tid & 3;
        float m = -1e30f;
        for (int c = sub; c < 512; c += 4) m = fmaxf(m, Sc[row*512 + c]);
        m = fmaxf(m, __shfl_xor_sync(0xffffffffu, m, 1));
        m = fmaxf(m, __shfl_xor_sync(0xffffffffu, m, 2));
        float s = 0.f;
        for (int c = sub; c < 512; c += 4) {
            float ev = __expf(Sc[row*512 + c] - m);
            Sc[row*512 + c] = ev; s += ev;
        }
        s += __shfl_xor_sync(0xffffffffu, s, 1);
        s += __shfl_xor_sync(0xffffffffu, s, 2);
        float inv = 1.f / s;
        for (int c = sub; c < 512; c += 4) Sc[row*512 + c] *= inv;
    }
    // ---- P @ V ----
    float acc[4][4] = {};
    for (int kb = 0; kb < 8; kb++) {
        const float* vbase = v + ((size_t)(b*SEQ + idx[kb]*64))*DMODEL + h*DHEAD;
        __syncthreads();
        for (int e = tid; e < 64*64; e += 256) {
            int r = e >> 6, d = e & 63;
            KV[r*68 + d] = vbase[(size_t)r*DMODEL + d];
        }
        __syncthreads();
        #pragma unroll 8
        for (int kk = 0; kk < 64; kk++) {
            float p[4], vv[4];
            #pragma unroll
            for (int i = 0; i < 4; i++) p[i] = Sc[(tr*4+i)*512 + kb*64 + kk];
            #pragma unroll
            for (int j = 0; j < 4; j++) vv[j] = KV[kk*68 + tc*4 + j];
            #pragma unroll
            for (int i = 0; i < 4; i++)
                #pragma unroll
                for (int j = 0; j < 4; j++)
                    acc[i][j] = fmaf(p[i], vv[j], acc[i][j]);
        }
    }
    float* obase = out + ((size_t)(b*SEQ + qb*64))*DMODEL + h*DHEAD;
    #pragma unroll
    for (int i = 0; i < 4; i++)
        #pragma unroll
        for (int j = 0; j < 4; j++)
            obase[(size_t)(tr*4+i)*DMODEL + tc*4 + j] = acc[i][j];
}

// ---------------- full attention for query blocks 0 and 63 ----------------
// scores: grid (64 kblocks, 2 rbi, B*H)
__global__ __launch_bounds__(256) void fa_scores(
    const float* __restrict__ q, const float* __restrict__ k, float* __restrict__ fs)
{
    __shared__ float Qt[64*68];
    __shared__ float Kt[64*68];
    int kb = blockIdx.x, rbi = blockIdx.y, bh = blockIdx.z;
    int b = bh / HEADS, h = bh % HEADS;
    int qb = rbi ? (NBLK-1) : 0;
    int tid = threadIdx.x;
    const float* qbase = q + ((size_t)(b*SEQ + qb*64))*DMODEL + h*DHEAD;
    const float* kbase = k + ((size_t)(b*SEQ + kb*64))*DMODEL + h*DHEAD;
    for (int e = tid; e < 64*64; e += 256) {
        int r = e >> 6, d = e & 63;
        Qt[d*68 + r] = qbase[(size_t)r*DMODEL + d];
        Kt[d*68 + r] = kbase[(size_t)r*DMODEL + d];
    }
    __syncthreads();
    int tr = tid >> 4, tc = tid & 15;
    float acc[4][4] = {};
    #pragma unroll 8
    for (int d = 0; d < 64; d++) {
        float a[4], bb[4];
        #pragma unroll
        for (int i = 0; i < 4; i++) a[i] = Qt[d*68 + tr*4 + i];
        #pragma unroll
        for (int j = 0; j < 4; j++) bb[j] = Kt[d*68 + tc*4 + j];
        #pragma unroll
        for (int i = 0; i < 4; i++)
            #pragma unroll
            for (int j = 0; j < 4; j++)
                acc[i][j] = fmaf(a[i], bb[j], acc[i][j]);
    }
    const float scale = 0.125f;
    float* orow = fs + ((size_t)(bh*2 + rbi)*64)*SEQ + kb*64;
    #pragma unroll
    for (int i = 0; i < 4; i++)
        #pragma unroll
        for (int j = 0; j < 4; j++)
            orow[(size_t)(tr*4+i)*SEQ + tc*4 + j] = acc[i][j] * scale;
}

__global__ __launch_bounds__(256) void fa_softmax(float* __restrict__ fs)
{
    __shared__ float red[8];
    float* rowp = fs + (size_t)blockIdx.x * SEQ;
    int tid = threadIdx.x;
    float m = -1e30f;
    for (int c = tid; c < SEQ; c += 256) m = fmaxf(m, rowp[c]);
    m = blockMax(m, red);
    float s = 0.f;
    for (int c = tid; c < SEQ; c += 256) {
        float ev = __expf(rowp[c] - m);
        rowp[c] = ev; s += ev;
    }
    s = blockSum(s, red);
    float inv = 1.f / s;
    for (int c = tid; c < SEQ; c += 256) rowp[c] *= inv;
}

// P@V for full rows: grid (2 rbi, B*H)
__global__ __launch_bounds__(256) void fa_pv(
    const float* __restrict__ fs, const float* __restrict__ v, float* __restrict__ out)
{
    __shared__ float Ps[64*68];
    __shared__ float Vs[64*68];
    int rbi = blockIdx.x, bh = blockIdx.y;
    int b = bh / HEADS, h = bh % HEADS;
    int qb = rbi ? (NBLK-1) : 0;
    int tid = threadIdx.x;
    int tr = tid >> 4, tc = tid & 15;
    float acc[4][4] = {};
    const float* prow = fs + ((size_t)(bh*2 + rbi)*64)*SEQ;
    for (int kb = 0; kb < NBLK; kb++) {
        const float* vbase = v + ((size_t)(b*SEQ + kb*64))*DMODEL + h*DHEAD;
        __syncthreads();
        for (int e = tid; e < 64*64; e += 256) {
            int r = e >> 6, c = e & 63;
            Ps[r*68 + c] = prow[(size_t)r*SEQ + kb*64 + c];
            Vs[r*68 + c] = vbase[(size_t)r*DMODEL + c];
        }
        __syncthreads();
        #pragma unroll 8
        for (int kk = 0; kk < 64; kk++) {
            float p[4], vv[4];
            #pragma unroll
            for (int i = 0; i < 4; i++) p[i] = Ps[(tr*4+i)*68 + kk];
            #pragma unroll
            for (int j = 0; j < 4; j++) vv[j] = Vs[kk*68 + tc*4 + j];
            #pragma unroll
            for (int i = 0; i < 4; i++)
                #pragma unroll
                for (int j = 0; j < 4; j++)
                    acc[i][j] = fmaf(p[i], vv[j], acc[i][j]);
        }
    }
    float* obase = out + ((size_t)(b*SEQ + qb*64))*DMODEL + h*DHEAD;
    #pragma unroll
    for (int i = 0; i < 4; i++)
        #pragma unroll
        for (int j = 0; j < 4; j++)
            obase[(size_t)(tr*4+i)*DMODEL + tc*4 + j] = acc[i][j];
}

// ---------------- mean pool + fc ----------------
__global__ __launch_bounds__(256) void pool1(const float* __restrict__ x, float* __restrict__ part)
{
    int c = blockIdx.x, b = blockIdx.y;
    int tid = threadIdx.x;
    #pragma unroll
    for (int i = 0; i < 3; i++) {
        int d = tid + i*256;
        const float* base = x + ((size_t)(b*SEQ + c*64))*DMODEL + d;
        float s = 0.f;
        #pragma unroll 8
        for (int t = 0; t < 64; t++) s += base[(size_t)t*DMODEL];
        part[((size_t)(b*64 + c))*DMODEL + d] = s;
    }
}

__global__ __launch_bounds__(256) void pool2(
    const float* __restrict__ part, const float* __restrict__ fcw,
    const float* __restrict__ fcb, float* __restrict__ out)
{
    __shared__ float red[8];
    int b = blockIdx.x, tid = threadIdx.x;
    float accv = 0.f;
    #pragma unroll
    for (int i = 0; i < 3; i++) {
        int d = tid + i*256;
        float s = 0.f;
        for (int c = 0; c < 64; c++) s += part[((size_t)(b*64 + c))*DMODEL + d];
        accv += (s * (1.f/SEQ)) * fcw[d];
    }
    float tot = blockSum(accv, red);
    if (tid == 0) out[b] = tot + fcb[0];
}

// ---------------- launch ----------------
extern "C" void kernel_launch(void* const* d_in, const int* in_sizes, int n_in,
                              void* d_out, int out_size)
{
    const int*   ids   = (const int*)  d_in[0];
    const int*   rnd   = (const int*)  d_in[1];
    const float* etok  = (const float*)d_in[2];
    const float* epos  = (const float*)d_in[3];
    const float* lng   = (const float*)d_in[4];
    const float* lnb   = (const float*)d_in[5];
    const float* Wq    = (const float*)d_in[6];
    const float* bq    = (const float*)d_in[7];
    const float* Wk    = (const float*)d_in[8];
    const float* bk    = (const float*)d_in[9];
    const float* Wv    = (const float*)d_in[10];
    const float* bv    = (const float*)d_in[11];
    const float* Wo    = (const float*)d_in[12];
    const float* bo    = (const float*)d_in[13];
    const float* ln1g  = (const float*)d_in[14];
    const float* ln1b  = (const float*)d_in[15];
    const float* W1    = (const float*)d_in[16];
    const float* b1    = (const float*)d_in[17];
    const float* W2    = (const float*)d_in[18];
    const float* b2    = (const float*)d_in[19];
    const float* ln2g  = (const float*)d_in[20];
    const float* ln2b  = (const float*)d_in[21];
    const float* fcw   = (const float*)d_in[22];
    const float* fcb   = (const float*)d_in[23];
    float* out = (float*)d_out;

    float *x, *q, *k, *v, *ao, *t, *h, *fs;
    cudaGetSymbolAddress((void**)&x,  g_x);
    cudaGetSymbolAddress((void**)&q,  g_q);
    cudaGetSymbolAddress((void**)&k,  g_k);
    cudaGetSymbolAddress((void**)&v,  g_v);
    cudaGetSymbolAddress((void**)&ao, g_ao);
    cudaGetSymbolAddress((void**)&t,  g_t);
    cudaGetSymbolAddress((void**)&h,  g_h);
    cudaGetSymbolAddress((void**)&fs, g_fs);

    cudaFuncSetAttribute(sparse_attn, cudaFuncAttributeMaxDynamicSharedMemorySize, SPARSE_SMEM);
    cudaFuncSetAttribute(gemm_tf32,   cudaFuncAttributeMaxDynamicSharedMemorySize, GEMM_SMEM);

    embed_ln<<<TOK, 256>>>(ids, etok, epos, lng, lnb, x);

    for (int l = 0; l < NLAYER; l++) {
        const float* Wql = Wq + (size_t)l*DMODEL*DMODEL;
        const float* Wkl = Wk + (size_t)l*DMODEL*DMODEL;
        const float* Wvl = Wv + (size_t)l*DMODEL*DMODEL;
        const float* Wol = Wo + (size_t)l*DMODEL*DMODEL;
        const float* W1l = W1 + (size_t)l*DMODEL*DFF;
        const float* W2l = W2 + (size_t)l*DFF*DMODEL;

        dim3 gQKV(DMODEL/128, TOK/128);
        gemm_tf32<<<gQKV, 256, GEMM_SMEM>>>(x, Wql, bq + l*DMODEL, q, TOK, DMODEL, DMODEL, 0);
        gemm_tf32<<<gQKV, 256, GEMM_SMEM>>>(x, Wkl, bk + l*DMODEL, k, TOK, DMODEL, DMODEL, 0);
        gemm_tf32<<<gQKV, 256, GEMM_SMEM>>>(x, Wvl, bv + l*DMODEL, v, TOK, DMODEL, DMODEL, 0);

        sparse_attn<<<dim3(NBLK-2, HEADS, BATCH), 256, SPARSE_SMEM>>>(q, k, v, rnd, ao);
        fa_scores<<<dim3(NBLK, 2, BATCH*HEADS), 256>>>(q, k, fs);
        fa_softmax<<<BATCH*HEADS*2*64, 256>>>(fs);
        fa_pv<<<dim3(2, BATCH*HEADS), 256>>>(fs, v, ao);

        gemm_tf32<<<gQKV, 256, GEMM_SMEM>>>(ao, Wol, bo + l*DMODEL, t, TOK, DMODEL, DMODEL, 0);
        add_ln<<<TOK, 256>>>(x, t, ln1g + l*DMODEL, ln1b + l*DMODEL);

        gemm_tf32<<<dim3(DFF/128, TOK/128), 256, GEMM_SMEM>>>(x, W1l, b1 + l*DFF, h, TOK, DFF, DMODEL, 1);
        gemm_tf32<<<dim3(DMODEL/128, TOK/128), 256, GEMM_SMEM>>>(h, W2l, b2 + l*DMODEL, t, TOK, DMODEL, DFF, 0);
        add_ln<<<TOK, 256>>>(x, t, ln2g + l*DMODEL, ln2b + l*DMODEL);
    }

    pool1<<<dim3(64, BATCH), 256>>>(x, fs);
    pool2<<<BATCH, 256>>>(fs, fcw, fcb, out);
}

// round 11
// speedup vs baseline: 2.7299x; 1.2661x over previous
#include <cuda_runtime.h>
#include <math.h>
#include <stdint.h>

#define DMODEL 768
#define HEADS 12
#define DHEAD 64
#define NLAYER 2
#define RRAND 3
#define BATCH 2
#define SEQ 4096
#define NBLK 64              // SEQ / 64
#define TOK (BATCH*SEQ)      // 8192
#define DFF (4*DMODEL)       // 3072

// ---------------- scratch (device globals; no runtime allocation) ----------------
__device__ float g_x  [TOK*DMODEL];
__device__ float g_xtf[TOK*DMODEL];           // tf32-rounded copy of x
__device__ float g_q  [TOK*DMODEL];
__device__ float g_k  [TOK*DMODEL];
__device__ float g_v  [TOK*DMODEL];
__device__ float g_ao [TOK*DMODEL];           // attention output (tf32-rounded)
__device__ float g_t  [TOK*DMODEL];
__device__ float g_h  [TOK*DFF];              // FFN hidden (tf32-rounded)
__device__ float g_fs [BATCH*HEADS*2*64*SEQ]; // full-attn scores / pool partials
// tf32-rounded weights: [Q | K | V | O | W1 | W2], each with L layers
#define WOFF_Q 0
#define WOFF_K (WOFF_Q + NLAYER*DMODEL*DMODEL)
#define WOFF_V (WOFF_K + NLAYER*DMODEL*DMODEL)
#define WOFF_O (WOFF_V + NLAYER*DMODEL*DMODEL)
#define WOFF_1 (WOFF_O + NLAYER*DMODEL*DMODEL)
#define WOFF_2 (WOFF_1 + NLAYER*DMODEL*DFF)
#define WTF_TOTAL (WOFF_2 + NLAYER*DFF*DMODEL)
__device__ float g_wtf[WTF_TOTAL];

// ---------------- tf32 helpers ----------------
__device__ __forceinline__ float f2tf_f(float x) {
    uint32_t u;
    asm("cvt.rna.tf32.f32 %0, %1;" : "=r"(u) : "f"(x));
    return __uint_as_float(u);
}
__device__ __forceinline__ void cpa16(void* dst, const void* src) {
    uint32_t d = (uint32_t)__cvta_generic_to_shared(dst);
    asm volatile("cp.async.cg.shared.global [%0], [%1], 16;" :: "r"(d), "l"(src));
}
__device__ __forceinline__ void mma_tf32(float* c, const uint32_t* a, const uint32_t* b) {
    asm volatile(
        "mma.sync.aligned.m16n8k8.row.col.f32.tf32.tf32.f32 "
        "{%0,%1,%2,%3},{%4,%5,%6,%7},{%8,%9},{%0,%1,%2,%3};"
        : "+f"(c[0]), "+f"(c[1]), "+f"(c[2]), "+f"(c[3])
        : "r"(a[0]), "r"(a[1]), "r"(a[2]), "r"(a[3]), "r"(b[0]), "r"(b[1]));
}

// vectorized tf32 pre-rounding: dst[i] = tf32(src[i]); n % 4 == 0
__global__ __launch_bounds__(256) void cvt_tf(const float* __restrict__ src,
                                              float* __restrict__ dst, int n)
{
    int i = (blockIdx.x*256 + threadIdx.x) * 4;
    if (i < n) {
        float4 v = *(const float4*)(src + i);
        v.x = f2tf_f(v.x); v.y = f2tf_f(v.y); v.z = f2tf_f(v.z); v.w = f2tf_f(v.w);
        *(float4*)(dst + i) = v;
    }
}

// ---------------- reductions ----------------
__device__ __forceinline__ float blockSum(float v, float* red) {
    __syncthreads();
    #pragma unroll
    for (int o = 16; o; o >>= 1) v += __shfl_down_sync(0xffffffffu, v, o);
    if ((threadIdx.x & 31) == 0) red[threadIdx.x >> 5] = v;
    __syncthreads();
    float r = (threadIdx.x < 8) ? red[threadIdx.x] : 0.f;
    if (threadIdx.x < 32) {
        #pragma unroll
        for (int o = 16; o; o >>= 1) r += __shfl_down_sync(0xffffffffu, r, o);
    }
    if (threadIdx.x == 0) red[0] = r;
    __syncthreads();
    return red[0];
}

__device__ __forceinline__ float blockMax(float v, float* red) {
    __syncthreads();
    #pragma unroll
    for (int o = 16; o; o >>= 1) v = fmaxf(v, __shfl_down_sync(0xffffffffu, v, o));
    if ((threadIdx.x & 31) == 0) red[threadIdx.x >> 5] = v;
    __syncthreads();
    float r = (threadIdx.x < 8) ? red[threadIdx.x] : -1e30f;
    if (threadIdx.x < 32) {
        #pragma unroll
        for (int o = 16; o; o >>= 1) r = fmaxf(r, __shfl_down_sync(0xffffffffu, r, o));
    }
    if (threadIdx.x == 0) red[0] = r;
    __syncthreads();
    return red[0];
}

// ---------------- embedding + layernorm (writes x and tf32 copy) ----------------
__global__ __launch_bounds__(256) void embed_ln(
    const int* __restrict__ ids, const float* __restrict__ etok,
    const float* __restrict__ epos, const float* __restrict__ g,
    const float* __restrict__ bi, float* __restrict__ x, float* __restrict__ xtf)
{
    __shared__ float red[8];
    int t = blockIdx.x;
    int s = t & (SEQ - 1);
    int tid = threadIdx.x;
    int id = ids[t];
    float e[3]; float sum = 0.f;
    #pragma unroll
    for (int i = 0; i < 3; i++) {
        int d = tid + i*256;
        e[i] = etok[(size_t)id*DMODEL + d] + epos[(size_t)s*DMODEL + d];
        sum += e[i];
    }
    float mean = blockSum(sum, red) * (1.f/DMODEL);
    float vs = 0.f;
    #pragma unroll
    for (int i = 0; i < 3; i++) { float df = e[i]-mean; vs += df*df; }
    float var = blockSum(vs, red) * (1.f/DMODEL);
    float inv = rsqrtf(var + 1e-12f);
    #pragma unroll
    for (int i = 0; i < 3; i++) {
        int d = tid + i*256;
        float o = (e[i]-mean)*inv*g[d] + bi[d];
        x  [(size_t)t*DMODEL + d] = o;
        xtf[(size_t)t*DMODEL + d] = f2tf_f(o);
    }
}

// ---------------- residual add + layernorm (in-place on x, tf32 copy out) ----------------
__global__ __launch_bounds__(256) void add_ln(
    float* __restrict__ x, const float* __restrict__ y,
    const float* __restrict__ g, const float* __restrict__ bi,
    float* __restrict__ xtf)
{
    __shared__ float red[8];
    int t = blockIdx.x;
    int tid = threadIdx.x;
    float e[3]; float sum = 0.f;
    #pragma unroll
    for (int i = 0; i < 3; i++) {
        int d = tid + i*256;
        e[i] = x[(size_t)t*DMODEL + d] + y[(size_t)t*DMODEL + d];
        sum += e[i];
    }
    float mean = blockSum(sum, red) * (1.f/DMODEL);
    float vs = 0.f;
    #pragma unroll
    for (int i = 0; i < 3; i++) { float df = e[i]-mean; vs += df*df; }
    float var = blockSum(vs, red) * (1.f/DMODEL);
    float inv = rsqrtf(var + 1e-12f);
    #pragma unroll
    for (int i = 0; i < 3; i++) {
        int d = tid + i*256;
        float o = (e[i]-mean)*inv*g[d] + bi[d];
        x  [(size_t)t*DMODEL + d] = o;
        xtf[(size_t)t*DMODEL + d] = f2tf_f(o);
    }
}

// ---------------- tf32 tensor-core GEMM (inputs pre-rounded; no in-loop CVT) ------------
// C[M,N] = A[M,K] @ B[K,N] + bias; act: GELU; cvtout: round result to tf32.
// BM=BN=128, BK=32, 256 threads. Warp grid 2(M)x4(N), warp tile 64x32 = 4x4 m16n8k8.
#define A_PAD 36
#define B_PAD 136
#define GEMM_SMEM ((2*128*A_PAD + 2*32*B_PAD) * 4)

__global__ __launch_bounds__(256, 2) void gemm_tf32(
    const float* __restrict__ A, const float* __restrict__ B,
    const float* __restrict__ bias, float* __restrict__ C,
    int M, int N, int K, int act, int cvtout)
{
    extern __shared__ float sm[];
    float* As = sm;                     // [2][128][A_PAD]
    float* Bs = sm + 2*128*A_PAD;       // [2][32][B_PAD]

    const int tid  = threadIdx.x;
    const int warp = tid >> 5, lane = tid & 31;
    const int g = lane >> 2, t = lane & 3;     // groupID, threadID-in-group
    const int wm = warp >> 2;                  // 0..1
    const int wn = warp & 3;                   // 0..3
    const int bm = blockIdx.y << 7;
    const int bn = blockIdx.x << 7;

    float acc[4][4][4] = {};

    auto load_stage = [&](int stg, int k0) {
        float* Ad = As + stg*128*A_PAD;
        float* Bd = Bs + stg*32*B_PAD;
        #pragma unroll
        for (int i = 0; i < 4; i++) {
            int f = tid + i*256;
            int r = f >> 3, c = (f & 7) << 2;
            cpa16(Ad + r*A_PAD + c, A + (size_t)(bm+r)*K + k0 + c);
            int br = f >> 5, bc = (f & 31) << 2;
            cpa16(Bd + br*B_PAD + bc, B + (size_t)(k0+br)*N + bn + bc);
        }
        asm volatile("cp.async.commit_group;" ::: "memory");
    };

    load_stage(0, 0);
    int stg = 0;
    for (int k0 = 0; k0 < K; k0 += 32, stg ^= 1) {
        if (k0 + 32 < K) {
            load_stage(stg ^ 1, k0 + 32);
            asm volatile("cp.async.wait_group 1;" ::: "memory");
        } else {
            asm volatile("cp.async.wait_group 0;" ::: "memory");
        }
        __syncthreads();

        const float* Ac = As + stg*128*A_PAD;
        const float* Bc = Bs + stg*32*B_PAD;
        #pragma unroll
        for (int ks = 0; ks < 4; ks++) {
            const int kb = ks*8;
            uint32_t af[4][4], bf[4][2];
            #pragma unroll
            for (int mt = 0; mt < 4; mt++) {
                int m = wm*64 + mt*16 + g;
                af[mt][0] = __float_as_uint(Ac[(m  )*A_PAD + kb + t    ]);
                af[mt][1] = __float_as_uint(Ac[(m+8)*A_PAD + kb + t    ]);
                af[mt][2] = __float_as_uint(Ac[(m  )*A_PAD + kb + t + 4]);
                af[mt][3] = __float_as_uint(Ac[(m+8)*A_PAD + kb + t + 4]);
            }
            #pragma unroll
            for (int nt = 0; nt < 4; nt++) {
                int n = wn*32 + nt*8 + g;
                bf[nt][0] = __float_as_uint(Bc[(kb + t    )*B_PAD + n]);
                bf[nt][1] = __float_as_uint(Bc[(kb + t + 4)*B_PAD + n]);
            }
            #pragma unroll
            for (int mt = 0; mt < 4; mt++)
                #pragma unroll
                for (int nt = 0; nt < 4; nt++)
                    mma_tf32(acc[mt][nt], af[mt], bf[nt]);
        }
        __syncthreads();
    }

    // epilogue
    #pragma unroll
    for (int mt = 0; mt < 4; mt++) {
        #pragma unroll
        for (int nt = 0; nt < 4; nt++) {
            int row = bm + wm*64 + mt*16 + g;
            int col = bn + wn*32 + nt*8 + t*2;
            float b0 = bias[col], b1 = bias[col+1];
            #pragma unroll
            for (int h = 0; h < 2; h++) {       // h=0: rows g, h=1: rows g+8
                float u0 = acc[mt][nt][2*h+0] + b0;
                float u1 = acc[mt][nt][2*h+1] + b1;
                if (act) {
                    u0 = 0.5f*u0*(1.f + tanhf(0.7978845608028654f*(u0 + 0.044715f*u0*u0*u0)));
                    u1 = 0.5f*u1*(1.f + tanhf(0.7978845608028654f*(u1 + 0.044715f*u1*u1*u1)));
                }
                if (cvtout) { u0 = f2tf_f(u0); u1 = f2tf_f(u1); }
                float2 p = make_float2(u0, u1);
                *(float2*)(C + (size_t)(row + 8*h)*N + col) = p;
            }
        }
    }
}

// ---------------- flash sparse block attention (query blocks 1..62) ----------------
// grid (62, H, B), 256 threads. Online softmax; P round-trips via 17KB smem tile.
// smem: Qt[64*68] + Kt[64*68] + Vs[64*68] + Ps[64*68] = 69632 B
#define SPARSE_SMEM (4*64*68*4)
__global__ __launch_bounds__(256, 2) void sparse_attn(
    const float* __restrict__ q, const float* __restrict__ k,
    const float* __restrict__ v, const int* __restrict__ rnd,
    float* __restrict__ out)
{
    extern __shared__ float sm[];
    float* Qt = sm;                 // [d][qr] stride 68
    float* Kt = sm + 64*68;         // [d][kc] stride 68
    float* Vs = sm + 2*64*68;       // [kc][d] stride 68
    float* Ps = sm + 3*64*68;       // [qr][kc] stride 68
    const int qb = blockIdx.x + 1;  // 1..62
    const int h = blockIdx.y, b = blockIdx.z;
    const int tid = threadIdx.x;
    const int tr = tid >> 4, tc = tid & 15;

    int idx[8];
    idx[0] = 0; idx[1] = qb-1; idx[2] = qb; idx[3] = qb+1; idx[4] = NBLK-1;
    #pragma unroll
    for (int j = 0; j < RRAND; j++)
        idx[5+j] = rnd[((size_t)h*NBLK + qb)*RRAND + j];

    const float scale = 0.125f;
    const float* qbase = q + ((size_t)(b*SEQ + qb*64))*DMODEL + h*DHEAD;
    for (int e = tid; e < 64*64; e += 256) {
        int r = e >> 6, d = e & 63;
        Qt[d*68 + r] = qbase[(size_t)r*DMODEL + d];
    }

    float m_run[4], l_run[4], o[4][4];
    #pragma unroll
    for (int i = 0; i < 4; i++) {
        m_run[i] = -1e30f; l_run[i] = 0.f;
        #pragma unroll
        for (int j = 0; j < 4; j++) o[i][j] = 0.f;
    }

    for (int kb = 0; kb < 8; kb++) {
        const float* kbase = k + ((size_t)(b*SEQ + idx[kb]*64))*DMODEL + h*DHEAD;
        const float* vbase = v + ((size_t)(b*SEQ + idx[kb]*64))*DMODEL + h*DHEAD;
        __syncthreads();   // prev iter's Kt/Vs/Ps consumption done
        for (int e = tid; e < 64*64; e += 256) {
            int r = e >> 6, d = e & 63;
            Kt[d*68 + r] = kbase[(size_t)r*DMODEL + d];
            Vs[r*68 + d] = vbase[(size_t)r*DMODEL + d];
        }
        __syncthreads();
        // scores S[4][4]
        float s[4][4] = {};
        #pragma unroll 8
        for (int d = 0; d < 64; d++) {
            float a[4], bb[4];
            #pragma unroll
            for (int i = 0; i < 4; i++) a[i] = Qt[d*68 + tr*4 + i];
            #pragma unroll
            for (int j = 0; j < 4; j++) bb[j] = Kt[d*68 + tc*4 + j];
            #pragma unroll
            for (int i = 0; i < 4; i++)
                #pragma unroll
                for (int j = 0; j < 4; j++)
                    s[i][j] = fmaf(a[i], bb[j], s[i][j]);
        }
        // online softmax update per row (16 lanes per row, same half-warp)
        #pragma unroll
        for (int i = 0; i < 4; i++) {
            float rm = -1e30f;
            #pragma unroll
            for (int j = 0; j < 4; j++) { s[i][j] *= scale; rm = fmaxf(rm, s[i][j]); }
            rm = fmaxf(rm, __shfl_xor_sync(0xffffffffu, rm, 1));
            rm = fmaxf(rm, __shfl_xor_sync(0xffffffffu, rm, 2));
            rm = fmaxf(rm, __shfl_xor_sync(0xffffffffu, rm, 4));
            rm = fmaxf(rm, __shfl_xor_sync(0xffffffffu, rm, 8));
            float mnew = fmaxf(m_run[i], rm);
            float fac = __expf(m_run[i] - mnew);
            float ps = 0.f;
            #pragma unroll
            for (int j = 0; j < 4; j++) {
                float p = __expf(s[i][j] - mnew);
                Ps[(tr*4+i)*68 + tc*4 + j] = p;
                ps += p;
            }
            ps += __shfl_xor_sync(0xffffffffu, ps, 1);
            ps += __shfl_xor_sync(0xffffffffu, ps, 2);
            ps += __shfl_xor_sync(0xffffffffu, ps, 4);
            ps += __shfl_xor_sync(0xffffffffu, ps, 8);
            l_run[i] = l_run[i]*fac + ps;
            m_run[i] = mnew;
            #pragma unroll
            for (int j = 0; j < 4; j++) o[i][j] *= fac;
        }
        __syncthreads();
        // o += P @ V
        #pragma unroll 8
        for (int kk = 0; kk < 64; kk++) {
            float p[4], vv[4];
            #pragma unroll
            for (int i = 0; i < 4; i++) p[i] = Ps[(tr*4+i)*68 + kk];
            #pragma unroll
            for (int j = 0; j < 4; j++) vv[j] = Vs[kk*68 + tc*4 + j];
            #pragma unroll
            for (int i = 0; i < 4; i++)
                #pragma unroll
                for (int j = 0; j < 4; j++)
                    o[i][j] = fmaf(p[i], vv[j], o[i][j]);
        }
    }
    float* obase = out + ((size_t)(b*SEQ + qb*64))*DMODEL + h*DHEAD;
    #pragma unroll
    for (int i = 0; i < 4; i++) {
        float inv = 1.f / l_run[i];
        #pragma unroll
        for (int j = 0; j < 4; j++)
            obase[(size_t)(tr*4+i)*DMODEL + tc*4 + j] = f2tf_f(o[i][j] * inv);
    }
}

// ---------------- full attention for query blocks 0 and 63 ----------------
__global__ __launch_bounds__(256) void fa_scores(
    const float* __restrict__ q, const float* __restrict__ k, float* __restrict__ fs)
{
    __shared__ float Qt[64*68];
    __shared__ float Kt[64*68];
    int kb = blockIdx.x, rbi = blockIdx.y, bh = blockIdx.z;
    int b = bh / HEADS, h = bh % HEADS;
    int qb = rbi ? (NBLK-1) : 0;
    int tid = threadIdx.x;
    const float* qbase = q + ((size_t)(b*SEQ + qb*64))*DMODEL + h*DHEAD;
    const float* kbase = k + ((size_t)(b*SEQ + kb*64))*DMODEL + h*DHEAD;
    for (int e = tid; e < 64*64; e += 256) {
        int r = e >> 6, d = e & 63;
        Qt[d*68 + r] = qbase[(size_t)r*DMODEL + d];
        Kt[d*68 + r] = kbase[(size_t)r*DMODEL + d];
    }
    __syncthreads();
    int tr = tid >> 4, tc = tid & 15;
    float acc[4][4] = {};
    #pragma unroll 8
    for (int d = 0; d < 64; d++) {
        float a[4], bb[4];
        #pragma unroll
        for (int i = 0; i < 4; i++) a[i] = Qt[d*68 + tr*4 + i];
        #pragma unroll
        for (int j = 0; j < 4; j++) bb[j] = Kt[d*68 + tc*4 + j];
        #pragma unroll
        for (int i = 0; i < 4; i++)
            #pragma unroll
            for (int j = 0; j < 4; j++)
                acc[i][j] = fmaf(a[i], bb[j], acc[i][j]);
    }
    const float scale = 0.125f;
    float* orow = fs + ((size_t)(bh*2 + rbi)*64)*SEQ + kb*64;
    #pragma unroll
    for (int i = 0; i < 4; i++)
        #pragma unroll
        for (int j = 0; j < 4; j++)
            orow[(size_t)(tr*4+i)*SEQ + tc*4 + j] = acc[i][j] * scale;
}

__global__ __launch_bounds__(256) void fa_softmax(float* __restrict__ fs)
{
    __shared__ float red[8];
    float* rowp = fs + (size_t)blockIdx.x * SEQ;
    int tid = threadIdx.x;
    float m = -1e30f;
    for (int c = tid; c < SEQ; c += 256) m = fmaxf(m, rowp[c]);
    m = blockMax(m, red);
    float s = 0.f;
    for (int c = tid; c < SEQ; c += 256) {
        float ev = __expf(rowp[c] - m);
        rowp[c] = ev; s += ev;
    }
    s = blockSum(s, red);
    float inv = 1.f / s;
    for (int c = tid; c < SEQ; c += 256) rowp[c] *= inv;
}

// P@V for full rows: grid (2 rbi, B*H)
__global__ __launch_bounds__(256) void fa_pv(
    const float* __restrict__ fs, const float* __restrict__ v, float* __restrict__ out)
{
    __shared__ float Ps[64*68];
    __shared__ float Vs[64*68];
    int rbi = blockIdx.x, bh = blockIdx.y;
    int b = bh / HEADS, h = bh % HEADS;
    int qb = rbi ? (NBLK-1) : 0;
    int tid = threadIdx.x;
    int tr = tid >> 4, tc = tid & 15;
    float acc[4][4] = {};
    const float* prow = fs + ((size_t)(bh*2 + rbi)*64)*SEQ;
    for (int kb = 0; kb < NBLK; kb++) {
        const float* vbase = v + ((size_t)(b*SEQ + kb*64))*DMODEL + h*DHEAD;
        __syncthreads();
        for (int e = tid; e < 64*64; e += 256) {
            int r = e >> 6, c = e & 63;
            Ps[r*68 + c] = prow[(size_t)r*SEQ + kb*64 + c];
            Vs[r*68 + c] = vbase[(size_t)r*DMODEL + c];
        }
        __syncthreads();
        #pragma unroll 8
        for (int kk = 0; kk < 64; kk++) {
            float p[4], vv[4];
            #pragma unroll
            for (int i = 0; i < 4; i++) p[i] = Ps[(tr*4+i)*68 + kk];
            #pragma unroll
            for (int j = 0; j < 4; j++) vv[j] = Vs[kk*68 + tc*4 + j];
            #pragma unroll
            for (int i = 0; i < 4; i++)
                #pragma unroll
                for (int j = 0; j < 4; j++)
                    acc[i][j] = fmaf(p[i], vv[j], acc[i][j]);
        }
    }
    float* obase = out + ((size_t)(b*SEQ + qb*64))*DMODEL + h*DHEAD;
    #pragma unroll
    for (int i = 0; i < 4; i++)
        #pragma unroll
        for (int j = 0; j < 4; j++)
            obase[(size_t)(tr*4+i)*DMODEL + tc*4 + j] = f2tf_f(acc[i][j]);
}

// ---------------- mean pool + fc ----------------
__global__ __launch_bounds__(256) void pool1(const float* __restrict__ x, float* __restrict__ part)
{
    int c = blockIdx.x, b = blockIdx.y;
    int tid = threadIdx.x;
    #pragma unroll
    for (int i = 0; i < 3; i++) {
        int d = tid + i*256;
        const float* base = x + ((size_t)(b*SEQ + c*64))*DMODEL + d;
        float s = 0.f;
        #pragma unroll 8
        for (int t = 0; t < 64; t++) s += base[(size_t)t*DMODEL];
        part[((size_t)(b*64 + c))*DMODEL + d] = s;
    }
}

__global__ __launch_bounds__(256) void pool2(
    const float* __restrict__ part, const float* __restrict__ fcw,
    const float* __restrict__ fcb, float* __restrict__ out)
{
    __shared__ float red[8];
    int b = blockIdx.x, tid = threadIdx.x;
    float accv = 0.f;
    #pragma unroll
    for (int i = 0; i < 3; i++) {
        int d = tid + i*256;
        float s = 0.f;
        for (int c = 0; c < 64; c++) s += part[((size_t)(b*64 + c))*DMODEL + d];
        accv += (s * (1.f/SEQ)) * fcw[d];
    }
    float tot = blockSum(accv, red);
    if (tid == 0) out[b] = tot + fcb[0];
}

// ---------------- launch ----------------
extern "C" void kernel_launch(void* const* d_in, const int* in_sizes, int n_in,
                              void* d_out, int out_size)
{
    const int*   ids   = (const int*)  d_in[0];
    const int*   rnd   = (const int*)  d_in[1];
    const float* etok  = (const float*)d_in[2];
    const float* epos  = (const float*)d_in[3];
    const float* lng   = (const float*)d_in[4];
    const float* lnb   = (const float*)d_in[5];
    const float* Wq    = (const float*)d_in[6];
    const float* bq    = (const float*)d_in[7];
    const float* Wk    = (const float*)d_in[8];
    const float* bk    = (const float*)d_in[9];
    const float* Wv    = (const float*)d_in[10];
    const float* bv    = (const float*)d_in[11];
    const float* Wo    = (const float*)d_in[12];
    const float* bo    = (const float*)d_in[13];
    const float* ln1g  = (const float*)d_in[14];
    const float* ln1b  = (const float*)d_in[15];
    const float* W1    = (const float*)d_in[16];
    const float* b1    = (const float*)d_in[17];
    const float* W2    = (const float*)d_in[18];
    const float* b2    = (const float*)d_in[19];
    const float* ln2g  = (const float*)d_in[20];
    const float* ln2b  = (const float*)d_in[21];
    const float* fcw   = (const float*)d_in[22];
    const float* fcb   = (const float*)d_in[23];
    float* out = (float*)d_out;

    float *x, *xtf, *q, *k, *v, *ao, *t, *h, *fs, *wtf;
    cudaGetSymbolAddress((void**)&x,   g_x);
    cudaGetSymbolAddress((void**)&xtf, g_xtf);
    cudaGetSymbolAddress((void**)&q,   g_q);
    cudaGetSymbolAddress((void**)&k,   g_k);
    cudaGetSymbolAddress((void**)&v,   g_v);
    cudaGetSymbolAddress((void**)&ao,  g_ao);
    cudaGetSymbolAddress((void**)&t,   g_t);
    cudaGetSymbolAddress((void**)&h,   g_h);
    cudaGetSymbolAddress((void**)&fs,  g_fs);
    cudaGetSymbolAddress((void**)&wtf, g_wtf);

    cudaFuncSetAttribute(sparse_attn, cudaFuncAttributeMaxDynamicSharedMemorySize, SPARSE_SMEM);
    cudaFuncSetAttribute(gemm_tf32,   cudaFuncAttributeMaxDynamicSharedMemorySize, GEMM_SMEM);

    // ---- pre-round all weights to tf32 (once per call) ----
    const int NSQ = NLAYER*DMODEL*DMODEL;      // 1179648
    const int NFF = NLAYER*DMODEL*DFF;         // 4718592
    cvt_tf<<<NSQ/1024, 256>>>(Wq, wtf + WOFF_Q, NSQ);
    cvt_tf<<<NSQ/1024, 256>>>(Wk, wtf + WOFF_K, NSQ);
    cvt_tf<<<NSQ/1024, 256>>>(Wv, wtf + WOFF_V, NSQ);
    cvt_tf<<<NSQ/1024, 256>>>(Wo, wtf + WOFF_O, NSQ);
    cvt_tf<<<NFF/1024, 256>>>(W1, wtf + WOFF_1, NFF);
    cvt_tf<<<NFF/1024, 256>>>(W2, wtf + WOFF_2, NFF);

    embed_ln<<<TOK, 256>>>(ids, etok, epos, lng, lnb, x, xtf);

    for (int l = 0; l < NLAYER; l++) {
        const float* Wql = wtf + WOFF_Q + (size_t)l*DMODEL*DMODEL;
        const float* Wkl = wtf + WOFF_K + (size_t)l*DMODEL*DMODEL;
        const float* Wvl = wtf + WOFF_V + (size_t)l*DMODEL*DMODEL;
        const float* Wol = wtf + WOFF_O + (size_t)l*DMODEL*DMODEL;
        const float* W1l = wtf + WOFF_1 + (size_t)l*DMODEL*DFF;
        const float* W2l = wtf + WOFF_2 + (size_t)l*DFF*DMODEL;

        dim3 gQKV(DMODEL/128, TOK/128);
        gemm_tf32<<<gQKV, 256, GEMM_SMEM>>>(xtf, Wql, bq + l*DMODEL, q, TOK, DMODEL, DMODEL, 0, 0);
        gemm_tf32<<<gQKV, 256, GEMM_SMEM>>>(xtf, Wkl, bk + l*DMODEL, k, TOK, DMODEL, DMODEL, 0, 0);
        gemm_tf32<<<gQKV, 256, GEMM_SMEM>>>(xtf, Wvl, bv + l*DMODEL, v, TOK, DMODEL, DMODEL, 0, 0);

        sparse_attn<<<dim3(NBLK-2, HEADS, BATCH), 256, SPARSE_SMEM>>>(q, k, v, rnd, ao);
        fa_scores<<<dim3(NBLK, 2, BATCH*HEADS), 256>>>(q, k, fs);
        fa_softmax<<<BATCH*HEADS*2*64, 256>>>(fs);
        fa_pv<<<dim3(2, BATCH*HEADS), 256>>>(fs, v, ao);

        gemm_tf32<<<gQKV, 256, GEMM_SMEM>>>(ao, Wol, bo + l*DMODEL, t, TOK, DMODEL, DMODEL, 0, 0);
        add_ln<<<TOK, 256>>>(x, t, ln1g + l*DMODEL, ln1b + l*DMODEL, xtf);

        gemm_tf32<<<dim3(DFF/128, TOK/128), 256, GEMM_SMEM>>>(xtf, W1l, b1 + l*DFF, h, TOK, DFF, DMODEL, 1, 1);
        gemm_tf32<<<dim3(DMODEL/128, TOK/128), 256, GEMM_SMEM>>>(h, W2l, b2 + l*DMODEL, t, TOK, DMODEL, DFF, 0, 0);
        add_ln<<<TOK, 256>>>(x, t, ln2g + l*DMODEL, ln2b + l*DMODEL, xtf);
    }

    pool1<<<dim3(64, BATCH), 256>>>(x, fs);
    pool2<<<BATCH, 256>>>(fs, fcw, fcb, out);
}

// round 12
// speedup vs baseline: 3.2704x; 1.1980x over previous
#include <cuda_runtime.h>
#include <math.h>
#include <stdint.h>

#define DMODEL 768
#define HEADS 12
#define DHEAD 64
#define NLAYER 2
#define RRAND 3
#define BATCH 2
#define SEQ 4096
#define NBLK 64              // SEQ / 64
#define TOK (BATCH*SEQ)      // 8192
#define DFF (4*DMODEL)       // 3072
#define NQKV (3*DMODEL)      // 2304

// ---------------- scratch (device globals; no runtime allocation) ----------------
__device__ float g_x  [TOK*DMODEL];
__device__ float g_xtf[TOK*DMODEL];           // tf32-rounded copy of x
__device__ float g_ao [TOK*DMODEL];           // attention output (tf32-rounded)
__device__ float g_t  [TOK*DMODEL];
__device__ float g_h  [TOK*DFF];              // FFN hidden / fused QKV output (time-shared)
__device__ float g_fs [BATCH*HEADS*2*64*SEQ]; // fa partials / pool partials
// tf32-rounded weights: [QKV packed | O | W1 | W2]
#define WOFF_QKV 0
#define WOFF_O (WOFF_QKV + NLAYER*DMODEL*NQKV)
#define WOFF_1 (WOFF_O + NLAYER*DMODEL*DMODEL)
#define WOFF_2 (WOFF_1 + NLAYER*DMODEL*DFF)
#define WTF_TOTAL (WOFF_2 + NLAYER*DFF*DMODEL)
__device__ float g_wtf[WTF_TOTAL];
__device__ float g_bqkv[NLAYER*NQKV];

// ---------------- tf32 helpers ----------------
__device__ __forceinline__ float f2tf_f(float x) {
    uint32_t u;
    asm("cvt.rna.tf32.f32 %0, %1;" : "=r"(u) : "f"(x));
    return __uint_as_float(u);
}
__device__ __forceinline__ void cpa16(void* dst, const void* src) {
    uint32_t d = (uint32_t)__cvta_generic_to_shared(dst);
    asm volatile("cp.async.cg.shared.global [%0], [%1], 16;" :: "r"(d), "l"(src));
}
__device__ __forceinline__ void mma_tf32(float* c, const uint32_t* a, const uint32_t* b) {
    asm volatile(
        "mma.sync.aligned.m16n8k8.row.col.f32.tf32.tf32.f32 "
        "{%0,%1,%2,%3},{%4,%5,%6,%7},{%8,%9},{%0,%1,%2,%3};"
        : "+f"(c[0]), "+f"(c[1]), "+f"(c[2]), "+f"(c[3])
        : "r"(a[0]), "r"(a[1]), "r"(a[2]), "r"(a[3]), "r"(b[0]), "r"(b[1]));
}

// vectorized tf32 pre-rounding: dst[i] = tf32(src[i]); n % 4 == 0
__global__ __launch_bounds__(256) void cvt_tf(const float* __restrict__ src,
                                              float* __restrict__ dst, int n)
{
    int i = (blockIdx.x*256 + threadIdx.x) * 4;
    if (i < n) {
        float4 v = *(const float4*)(src + i);
        v.x = f2tf_f(v.x); v.y = f2tf_f(v.y); v.z = f2tf_f(v.z); v.w = f2tf_f(v.w);
        *(float4*)(dst + i) = v;
    }
}

// pack Wq|Wk|Wv into [L][768][2304], tf32-rounded
__global__ __launch_bounds__(256) void pack_qkv(
    const float* __restrict__ Wq, const float* __restrict__ Wk,
    const float* __restrict__ Wv, float* __restrict__ dst)
{
    int idx = blockIdx.x*256 + threadIdx.x;
    if (idx >= NLAYER*DMODEL*NQKV) return;
    int l = idx / (DMODEL*NQKV);
    int r = idx % (DMODEL*NQKV);
    int k = r / NQKV, n = r % NQKV;
    float s;
    size_t base = ((size_t)l*DMODEL + k)*DMODEL;
    if (n < DMODEL)           s = Wq[base + n];
    else if (n < 2*DMODEL)    s = Wk[base + n - DMODEL];
    else                      s = Wv[base + n - 2*DMODEL];
    dst[idx] = f2tf_f(s);
}

__global__ __launch_bounds__(256) void pack_bias(
    const float* __restrict__ bq, const float* __restrict__ bk,
    const float* __restrict__ bv, float* __restrict__ dst)
{
    int idx = blockIdx.x*256 + threadIdx.x;
    if (idx >= NLAYER*NQKV) return;
    int l = idx / NQKV, n = idx % NQKV;
    float s;
    if (n < DMODEL)           s = bq[l*DMODEL + n];
    else if (n < 2*DMODEL)    s = bk[l*DMODEL + n - DMODEL];
    else                      s = bv[l*DMODEL + n - 2*DMODEL];
    dst[idx] = s;
}

// ---------------- reductions ----------------
__device__ __forceinline__ float blockSum(float v, float* red) {
    __syncthreads();
    #pragma unroll
    for (int o = 16; o; o >>= 1) v += __shfl_down_sync(0xffffffffu, v, o);
    if ((threadIdx.x & 31) == 0) red[threadIdx.x >> 5] = v;
    __syncthreads();
    float r = (threadIdx.x < 8) ? red[threadIdx.x] : 0.f;
    if (threadIdx.x < 32) {
        #pragma unroll
        for (int o = 16; o; o >>= 1) r += __shfl_down_sync(0xffffffffu, r, o);
    }
    if (threadIdx.x == 0) red[0] = r;
    __syncthreads();
    return red[0];
}

// ---------------- embedding + layernorm (writes x and tf32 copy) ----------------
__global__ __launch_bounds__(256) void embed_ln(
    const int* __restrict__ ids, const float* __restrict__ etok,
    const float* __restrict__ epos, const float* __restrict__ g,
    const float* __restrict__ bi, float* __restrict__ x, float* __restrict__ xtf)
{
    __shared__ float red[8];
    int t = blockIdx.x;
    int s = t & (SEQ - 1);
    int tid = threadIdx.x;
    int id = ids[t];
    float e[3]; float sum = 0.f;
    #pragma unroll
    for (int i = 0; i < 3; i++) {
        int d = tid + i*256;
        e[i] = etok[(size_t)id*DMODEL + d] + epos[(size_t)s*DMODEL + d];
        sum += e[i];
    }
    float mean = blockSum(sum, red) * (1.f/DMODEL);
    float vs = 0.f;
    #pragma unroll
    for (int i = 0; i < 3; i++) { float df = e[i]-mean; vs += df*df; }
    float var = blockSum(vs, red) * (1.f/DMODEL);
    float inv = rsqrtf(var + 1e-12f);
    #pragma unroll
    for (int i = 0; i < 3; i++) {
        int d = tid + i*256;
        float o = (e[i]-mean)*inv*g[d] + bi[d];
        x  [(size_t)t*DMODEL + d] = o;
        xtf[(size_t)t*DMODEL + d] = f2tf_f(o);
    }
}

// ---------------- residual add + layernorm (in-place on x, tf32 copy out) ----------------
__global__ __launch_bounds__(256) void add_ln(
    float* __restrict__ x, const float* __restrict__ y,
    const float* __restrict__ g, const float* __restrict__ bi,
    float* __restrict__ xtf)
{
    __shared__ float red[8];
    int t = blockIdx.x;
    int tid = threadIdx.x;
    float e[3]; float sum = 0.f;
    #pragma unroll
    for (int i = 0; i < 3; i++) {
        int d = tid + i*256;
        e[i] = x[(size_t)t*DMODEL + d] + y[(size_t)t*DMODEL + d];
        sum += e[i];
    }
    float mean = blockSum(sum, red) * (1.f/DMODEL);
    float vs = 0.f;
    #pragma unroll
    for (int i = 0; i < 3; i++) { float df = e[i]-mean; vs += df*df; }
    float var = blockSum(vs, red) * (1.f/DMODEL);
    float inv = rsqrtf(var + 1e-12f);
    #pragma unroll
    for (int i = 0; i < 3; i++) {
        int d = tid + i*256;
        float o = (e[i]-mean)*inv*g[d] + bi[d];
        x  [(size_t)t*DMODEL + d] = o;
        xtf[(size_t)t*DMODEL + d] = f2tf_f(o);
    }
}

// ---------------- tf32 tensor-core GEMM, 3-stage pipeline ----------------
// C[M,N] = A[M,K] @ B[K,N] + bias; act: GELU; cvtout: round result to tf32.
// BM=BN=128, BK=32, 256 threads. Warp grid 2(M)x4(N), warp tile 64x32 = 4x4 m16n8k8.
#define A_PAD 36
#define B_PAD 136
#define STG_FLT (128*A_PAD + 32*B_PAD)
#define GEMM_SMEM (3*STG_FLT*4)

__global__ __launch_bounds__(256, 2) void gemm_tf32(
    const float* __restrict__ A, const float* __restrict__ B,
    const float* __restrict__ bias, float* __restrict__ C,
    int M, int N, int K, int act, int cvtout)
{
    extern __shared__ float sm[];

    const int tid  = threadIdx.x;
    const int warp = tid >> 5, lane = tid & 31;
    const int g = lane >> 2, t = lane & 3;     // groupID, threadID-in-group
    const int wm = warp >> 2;                  // 0..1
    const int wn = warp & 3;                   // 0..3
    const int bm = blockIdx.y << 7;
    const int bn = blockIdx.x << 7;

    float acc[4][4][4] = {};

    auto load_stage = [&](int stg, int k0) {
        float* Ad = sm + stg*STG_FLT;
        float* Bd = Ad + 128*A_PAD;
        #pragma unroll
        for (int i = 0; i < 4; i++) {
            int f = tid + i*256;
            int r = f >> 3, c = (f & 7) << 2;
            cpa16(Ad + r*A_PAD + c, A + (size_t)(bm+r)*K + k0 + c);
            int br = f >> 5, bc = (f & 31) << 2;
            cpa16(Bd + br*B_PAD + bc, B + (size_t)(k0+br)*N + bn + bc);
        }
        asm volatile("cp.async.commit_group;" ::: "memory");
    };

    const int nk = K >> 5;
    load_stage(0, 0);
    load_stage(1, 32);

    for (int it = 0; it < nk; it++) {
        int s = it - (it >= 3 ? (it/3)*3 : 0);  // it % 3
        s = it % 3;
        if (it + 1 < nk) { asm volatile("cp.async.wait_group 1;" ::: "memory"); }
        else             { asm volatile("cp.async.wait_group 0;" ::: "memory"); }
        __syncthreads();
        if (it + 2 < nk) load_stage((it+2)%3, (it+2) << 5);

        const float* Ac = sm + s*STG_FLT;
        const float* Bc = Ac + 128*A_PAD;
        #pragma unroll
        for (int ks = 0; ks < 4; ks++) {
            const int kb = ks*8;
            uint32_t af[4][4], bf[4][2];
            #pragma unroll
            for (int mt = 0; mt < 4; mt++) {
                int m = wm*64 + mt*16 + g;
                af[mt][0] = __float_as_uint(Ac[(m  )*A_PAD + kb + t    ]);
                af[mt][1] = __float_as_uint(Ac[(m+8)*A_PAD + kb + t    ]);
                af[mt][2] = __float_as_uint(Ac[(m  )*A_PAD + kb + t + 4]);
                af[mt][3] = __float_as_uint(Ac[(m+8)*A_PAD + kb + t + 4]);
            }
            #pragma unroll
            for (int nt = 0; nt < 4; nt++) {
                int n = wn*32 + nt*8 + g;
                bf[nt][0] = __float_as_uint(Bc[(kb + t    )*B_PAD + n]);
                bf[nt][1] = __float_as_uint(Bc[(kb + t + 4)*B_PAD + n]);
            }
            #pragma unroll
            for (int mt = 0; mt < 4; mt++)
                #pragma unroll
                for (int nt = 0; nt < 4; nt++)
                    mma_tf32(acc[mt][nt], af[mt], bf[nt]);
        }
    }

    // epilogue
    #pragma unroll
    for (int mt = 0; mt < 4; mt++) {
        #pragma unroll
        for (int nt = 0; nt < 4; nt++) {
            int row = bm + wm*64 + mt*16 + g;
            int col = bn + wn*32 + nt*8 + t*2;
            float b0 = bias[col], b1 = bias[col+1];
            #pragma unroll
            for (int h = 0; h < 2; h++) {       // h=0: rows g, h=1: rows g+8
                float u0 = acc[mt][nt][2*h+0] + b0;
                float u1 = acc[mt][nt][2*h+1] + b1;
                if (act) {
                    u0 = 0.5f*u0*(1.f + tanhf(0.7978845608028654f*(u0 + 0.044715f*u0*u0*u0)));
                    u1 = 0.5f*u1*(1.f + tanhf(0.7978845608028654f*(u1 + 0.044715f*u1*u1*u1)));
                }
                if (cvtout) { u0 = f2tf_f(u0); u1 = f2tf_f(u1); }
                float2 p = make_float2(u0, u1);
                *(float2*)(C + (size_t)(row + 8*h)*N + col) = p;
            }
        }
    }
}

// ---------------- flash attention core (shared by sparse + full-split) ----------------
// smem: Qt[64*68] + Kt[64*68] + Vs[64*68] + Ps[64*68] = 69632 B
#define SPARSE_SMEM (4*64*68*4)

// Computes flash over 8 key blocks given by idx[]; returns unnormalized o + (m,l).
// q/k/v pointers have row stride `str`.
__device__ __forceinline__ void flash8(
    const float* q, const float* k, const float* v, int str,
    int b, int h, int qb, const int* idx,
    float* sm, float o[4][4], float m_run[4], float l_run[4])
{
    float* Qt = sm;                 // [d][qr] stride 68
    float* Kt = sm + 64*68;         // [d][kc] stride 68
    float* Vs = sm + 2*64*68;       // [kc][d] stride 68
    float* Ps = sm + 3*64*68;       // [qr][kc] stride 68
    const int tid = threadIdx.x;
    const int tr = tid >> 4, tc = tid & 15;
    const float scale = 0.125f;

    const float* qbase = q + ((size_t)(b*SEQ + qb*64))*str + h*DHEAD;
    for (int e = tid; e < 64*64; e += 256) {
        int r = e >> 6, d = e & 63;
        Qt[d*68 + r] = qbase[(size_t)r*str + d];
    }

    #pragma unroll
    for (int i = 0; i < 4; i++) {
        m_run[i] = -1e30f; l_run[i] = 0.f;
        #pragma unroll
        for (int j = 0; j < 4; j++) o[i][j] = 0.f;
    }

    for (int kb = 0; kb < 8; kb++) {
        const float* kbase = k + ((size_t)(b*SEQ + idx[kb]*64))*str + h*DHEAD;
        const float* vbase = v + ((size_t)(b*SEQ + idx[kb]*64))*str + h*DHEAD;
        __syncthreads();
        for (int e = tid; e < 64*64; e += 256) {
            int r = e >> 6, d = e & 63;
            Kt[d*68 + r] = kbase[(size_t)r*str + d];
            Vs[r*68 + d] = vbase[(size_t)r*str + d];
        }
        __syncthreads();
        float s[4][4] = {};
        #pragma unroll 8
        for (int d = 0; d < 64; d++) {
            float a[4], bb[4];
            #pragma unroll
            for (int i = 0; i < 4; i++) a[i] = Qt[d*68 + tr*4 + i];
            #pragma unroll
            for (int j = 0; j < 4; j++) bb[j] = Kt[d*68 + tc*4 + j];
            #pragma unroll
            for (int i = 0; i < 4; i++)
                #pragma unroll
                for (int j = 0; j < 4; j++)
                    s[i][j] = fmaf(a[i], bb[j], s[i][j]);
        }
        #pragma unroll
        for (int i = 0; i < 4; i++) {
            float rm = -1e30f;
            #pragma unroll
            for (int j = 0; j < 4; j++) { s[i][j] *= scale; rm = fmaxf(rm, s[i][j]); }
            rm = fmaxf(rm, __shfl_xor_sync(0xffffffffu, rm, 1));
            rm = fmaxf(rm, __shfl_xor_sync(0xffffffffu, rm, 2));
            rm = fmaxf(rm, __shfl_xor_sync(0xffffffffu, rm, 4));
            rm = fmaxf(rm, __shfl_xor_sync(0xffffffffu, rm, 8));
            float mnew = fmaxf(m_run[i], rm);
            float fac = __expf(m_run[i] - mnew);
            float ps = 0.f;
            #pragma unroll
            for (int j = 0; j < 4; j++) {
                float p = __expf(s[i][j] - mnew);
                Ps[(tr*4+i)*68 + tc*4 + j] = p;
                ps += p;
            }
            ps += __shfl_xor_sync(0xffffffffu, ps, 1);
            ps += __shfl_xor_sync(0xffffffffu, ps, 2);
            ps += __shfl_xor_sync(0xffffffffu, ps, 4);
            ps += __shfl_xor_sync(0xffffffffu, ps, 8);
            l_run[i] = l_run[i]*fac + ps;
            m_run[i] = mnew;
            #pragma unroll
            for (int j = 0; j < 4; j++) o[i][j] *= fac;
        }
        __syncthreads();
        #pragma unroll 8
        for (int kk = 0; kk < 64; kk++) {
            float p[4], vv[4];
            #pragma unroll
            for (int i = 0; i < 4; i++) p[i] = Ps[(tr*4+i)*68 + kk];
            #pragma unroll
            for (int j = 0; j < 4; j++) vv[j] = Vs[kk*68 + tc*4 + j];
            #pragma unroll
            for (int i = 0; i < 4; i++)
                #pragma unroll
                for (int j = 0; j < 4; j++)
                    o[i][j] = fmaf(p[i], vv[j], o[i][j]);
        }
    }
}

// sparse block attention: query blocks 1..62, grid (62, H, B)
__global__ __launch_bounds__(256, 2) void sparse_attn(
    const float* __restrict__ q, const float* __restrict__ k,
    const float* __restrict__ v, int str, const int* __restrict__ rnd,
    float* __restrict__ out)
{
    extern __shared__ float sm[];
    const int qb = blockIdx.x + 1;
    const int h = blockIdx.y, b = blockIdx.z;
    const int tid = threadIdx.x;
    const int tr = tid >> 4, tc = tid & 15;

    int idx[8];
    idx[0] = 0; idx[1] = qb-1; idx[2] = qb; idx[3] = qb+1; idx[4] = NBLK-1;
    #pragma unroll
    for (int j = 0; j < RRAND; j++)
        idx[5+j] = rnd[((size_t)h*NBLK + qb)*RRAND + j];

    float o[4][4], m_run[4], l_run[4];
    flash8(q, k, v, str, b, h, qb, idx, sm, o, m_run, l_run);

    float* obase = out + ((size_t)(b*SEQ + qb*64))*DMODEL + h*DHEAD;
    #pragma unroll
    for (int i = 0; i < 4; i++) {
        float inv = 1.f / l_run[i];
        #pragma unroll
        for (int j = 0; j < 4; j++)
            obase[(size_t)(tr*4+i)*DMODEL + tc*4 + j] = f2tf_f(o[i][j] * inv);
    }
}

// full-attention partials: grid (8 splits, 2 rbi, B*H). Each CTA: 8 key blocks.
// partial layout per (bh,rbi,split): [64*64 o | 64 m | 64 l] = 4224 floats
__global__ __launch_bounds__(256, 2) void fa_part(
    const float* __restrict__ q, const float* __restrict__ k,
    const float* __restrict__ v, int str, float* __restrict__ fs)
{
    extern __shared__ float sm[];
    const int split = blockIdx.x, rbi = blockIdx.y, bh = blockIdx.z;
    const int b = bh / HEADS, h = bh % HEADS;
    const int qb = rbi ? (NBLK-1) : 0;
    const int tid = threadIdx.x;
    const int tr = tid >> 4, tc = tid & 15;

    int idx[8];
    #pragma unroll
    for (int j = 0; j < 8; j++) idx[j] = split*8 + j;

    float o[4][4], m_run[4], l_run[4];
    flash8(q, k, v, str, b, h, qb, idx, sm, o, m_run, l_run);

    float* pb = fs + ((size_t)((bh*2 + rbi)*8 + split)) * 4224;
    #pragma unroll
    for (int i = 0; i < 4; i++) {
        #pragma unroll
        for (int j = 0; j < 4; j++)
            pb[(tr*4+i)*64 + tc*4 + j] = o[i][j];
        if (tc == 0) {
            pb[4096 + tr*4 + i] = m_run[i];
            pb[4160 + tr*4 + i] = l_run[i];
        }
    }
}

// combine 8 partials: grid (2, B*H), 256 threads (4 threads per row, 16 cols each)
__global__ __launch_bounds__(256) void fa_reduce(
    const float* __restrict__ fs, float* __restrict__ out)
{
    const int rbi = blockIdx.x, bh = blockIdx.y;
    const int b = bh / HEADS, h = bh % HEADS;
    const int qb = rbi ? (NBLK-1) : 0;
    const int tid = threadIdx.x;
    const int row = tid >> 2, cg = (tid & 3) * 16;
    const float* base = fs + ((size_t)(bh*2 + rbi)*8) * 4224;

    float pm[8], pl[8], M = -1e30f;
    #pragma unroll
    for (int s = 0; s < 8; s++) {
        pm[s] = base[s*4224 + 4096 + row];
        pl[s] = base[s*4224 + 4160 + row];
        M = fmaxf(M, pm[s]);
    }
    float f[8], L = 0.f;
    #pragma unroll
    for (int s = 0; s < 8; s++) { f[s] = __expf(pm[s] - M); L += pl[s]*f[s]; }
    float invL = 1.f / L;

    float* obase = out + ((size_t)(b*SEQ + qb*64 + row))*DMODEL + h*DHEAD;
    #pragma unroll
    for (int c = 0; c < 16; c++) {
        float o = 0.f;
        #pragma unroll
        for (int s = 0; s < 8; s++)
            o += base[s*4224 + row*64 + cg + c] * f[s];
        obase[cg + c] = f2tf_f(o * invL);
    }
}

// ---------------- mean pool + fc ----------------
__global__ __launch_bounds__(256) void pool1(const float* __restrict__ x, float* __restrict__ part)
{
    int c = blockIdx.x, b = blockIdx.y;
    int tid = threadIdx.x;
    #pragma unroll
    for (int i = 0; i < 3; i++) {
        int d = tid + i*256;
        const float* base = x + ((size_t)(b*SEQ + c*64))*DMODEL + d;
        float s = 0.f;
        #pragma unroll 8
        for (int t = 0; t < 64; t++) s += base[(size_t)t*DMODEL];
        part[((size_t)(b*64 + c))*DMODEL + d] = s;
    }
}

__global__ __launch_bounds__(256) void pool2(
    const float* __restrict__ part, const float* __restrict__ fcw,
    const float* __restrict__ fcb, float* __restrict__ out)
{
    __shared__ float red[8];
    int b = blockIdx.x, tid = threadIdx.x;
    float accv = 0.f;
    #pragma unroll
    for (int i = 0; i < 3; i++) {
        int d = tid + i*256;
        float s = 0.f;
        for (int c = 0; c < 64; c++) s += part[((size_t)(b*64 + c))*DMODEL + d];
        accv += (s * (1.f/SEQ)) * fcw[d];
    }
    float tot = blockSum(accv, red);
    if (tid == 0) out[b] = tot + fcb[0];
}

// ---------------- launch ----------------
extern "C" void kernel_launch(void* const* d_in, const int* in_sizes, int n_in,
                              void* d_out, int out_size)
{
    const int*   ids   = (const int*)  d_in[0];
    const int*   rnd   = (const int*)  d_in[1];
    const float* etok  = (const float*)d_in[2];
    const float* epos  = (const float*)d_in[3];
    const float* lng   = (const float*)d_in[4];
    const float* lnb   = (const float*)d_in[5];
    const float* Wq    = (const float*)d_in[6];
    const float* bq    = (const float*)d_in[7];
    const float* Wk    = (const float*)d_in[8];
    const float* bk    = (const float*)d_in[9];
    const float* Wv    = (const float*)d_in[10];
    const float* bv    = (const float*)d_in[11];
    const float* Wo    = (const float*)d_in[12];
    const float* bo    = (const float*)d_in[13];
    const float* ln1g  = (const float*)d_in[14];
    const float* ln1b  = (const float*)d_in[15];
    const float* W1    = (const float*)d_in[16];
    const float* b1    = (const float*)d_in[17];
    const float* W2    = (const float*)d_in[18];
    const float* b2    = (const float*)d_in[19];
    const float* ln2g  = (const float*)d_in[20];
    const float* ln2b  = (const float*)d_in[21];
    const float* fcw   = (const float*)d_in[22];
    const float* fcb   = (const float*)d_in[23];
    float* out = (float*)d_out;

    float *x, *xtf, *ao, *t, *h, *fs, *wtf, *bqkv;
    cudaGetSymbolAddress((void**)&x,    g_x);
    cudaGetSymbolAddress((void**)&xtf,  g_xtf);
    cudaGetSymbolAddress((void**)&ao,   g_ao);
    cudaGetSymbolAddress((void**)&t,    g_t);
    cudaGetSymbolAddress((void**)&h,    g_h);
    cudaGetSymbolAddress((void**)&fs,   g_fs);
    cudaGetSymbolAddress((void**)&wtf,  g_wtf);
    cudaGetSymbolAddress((void**)&bqkv, g_bqkv);

    cudaFuncSetAttribute(sparse_attn, cudaFuncAttributeMaxDynamicSharedMemorySize, SPARSE_SMEM);
    cudaFuncSetAttribute(fa_part,     cudaFuncAttributeMaxDynamicSharedMemorySize, SPARSE_SMEM);
    cudaFuncSetAttribute(gemm_tf32,   cudaFuncAttributeMaxDynamicSharedMemorySize, GEMM_SMEM);

    // ---- pre-round / pack weights (once per call) ----
    const int NSQ = NLAYER*DMODEL*DMODEL;
    const int NFF = NLAYER*DMODEL*DFF;
    pack_qkv<<<(NLAYER*DMODEL*NQKV + 255)/256, 256>>>(Wq, Wk, Wv, wtf + WOFF_QKV);
    pack_bias<<<(NLAYER*NQKV + 255)/256, 256>>>(bq, bk, bv, bqkv);
    cvt_tf<<<NSQ/1024, 256>>>(Wo, wtf + WOFF_O, NSQ);
    cvt_tf<<<NFF/1024, 256>>>(W1, wtf + WOFF_1, NFF);
    cvt_tf<<<NFF/1024, 256>>>(W2, wtf + WOFF_2, NFF);

    embed_ln<<<TOK, 256>>>(ids, etok, epos, lng, lnb, x, xtf);

    for (int l = 0; l < NLAYER; l++) {
        const float* Wqkvl = wtf + WOFF_QKV + (size_t)l*DMODEL*NQKV;
        const float* Wol   = wtf + WOFF_O   + (size_t)l*DMODEL*DMODEL;
        const float* W1l   = wtf + WOFF_1   + (size_t)l*DMODEL*DFF;
        const float* W2l   = wtf + WOFF_2   + (size_t)l*DFF*DMODEL;

        // fused QKV: output in g_h (row stride 2304)
        gemm_tf32<<<dim3(NQKV/128, TOK/128), 256, GEMM_SMEM>>>(
            xtf, Wqkvl, bqkv + l*NQKV, h, TOK, NQKV, DMODEL, 0, 0);

        const float* q = h, *k = h + DMODEL, *v = h + 2*DMODEL;
        sparse_attn<<<dim3(NBLK-2, HEADS, BATCH), 256, SPARSE_SMEM>>>(q, k, v, NQKV, rnd, ao);
        fa_part<<<dim3(8, 2, BATCH*HEADS), 256, SPARSE_SMEM>>>(q, k, v, NQKV, fs);
        fa_reduce<<<dim3(2, BATCH*HEADS), 256>>>(fs, ao);

        gemm_tf32<<<dim3(DMODEL/128, TOK/128), 256, GEMM_SMEM>>>(
            ao, Wol, bo + l*DMODEL, t, TOK, DMODEL, DMODEL, 0, 0);
        add_ln<<<TOK, 256>>>(x, t, ln1g + l*DMODEL, ln1b + l*DMODEL, xtf);

        gemm_tf32<<<dim3(DFF/128, TOK/128), 256, GEMM_SMEM>>>(
            xtf, W1l, b1 + l*DFF, h, TOK, DFF, DMODEL, 1, 1);
        gemm_tf32<<<dim3(DMODEL/128, TOK/128), 256, GEMM_SMEM>>>(
            h, W2l, b2 + l*DMODEL, t, TOK, DMODEL, DFF, 0, 0);
        add_ln<<<TOK, 256>>>(x, t, ln2g + l*DMODEL, ln2b + l*DMODEL, xtf);
    }

    pool1<<<dim3(64, BATCH), 256>>>(x, fs);
    pool2<<<BATCH, 256>>>(fs, fcw, fcb, out);
}

// round 13
// speedup vs baseline: 3.2778x; 1.0023x over previous
#include <cuda_runtime.h>
#include <math.h>
#include <stdint.h>

#define DMODEL 768
#define HEADS 12
#define DHEAD 64
#define NLAYER 2
#define RRAND 3
#define BATCH 2
#define SEQ 4096
#define NBLK 64              // SEQ / 64
#define TOK (BATCH*SEQ)      // 8192
#define DFF (4*DMODEL)       // 3072
#define NQKV (3*DMODEL)      // 2304

// ---------------- scratch (device globals; no runtime allocation) ----------------
__device__ float g_x  [TOK*DMODEL];
__device__ float g_xtf[TOK*DMODEL];           // tf32-rounded copy of x
__device__ float g_ao [TOK*DMODEL];           // attention output (tf32-rounded)
__device__ float g_t  [TOK*DMODEL];
__device__ float g_h  [TOK*DFF];              // FFN hidden / fused QKV output (time-shared)
__device__ float g_fs [BATCH*HEADS*2*64*SEQ]; // fa partials / pool partials
// tf32-rounded weights: [QKV packed | O | W1 | W2]
#define WOFF_QKV 0
#define WOFF_O (WOFF_QKV + NLAYER*DMODEL*NQKV)
#define WOFF_1 (WOFF_O + NLAYER*DMODEL*DMODEL)
#define WOFF_2 (WOFF_1 + NLAYER*DMODEL*DFF)
#define WTF_TOTAL (WOFF_2 + NLAYER*DFF*DMODEL)
__device__ float g_wtf[WTF_TOTAL];
__device__ float g_bqkv[NLAYER*NQKV];

// ---------------- tf32 helpers ----------------
__device__ __forceinline__ float f2tf_f(float x) {
    uint32_t u;
    asm("cvt.rna.tf32.f32 %0, %1;" : "=r"(u) : "f"(x));
    return __uint_as_float(u);
}
__device__ __forceinline__ void cpa16(void* dst, const void* src) {
    uint32_t d = (uint32_t)__cvta_generic_to_shared(dst);
    asm volatile("cp.async.cg.shared.global [%0], [%1], 16;" :: "r"(d), "l"(src));
}
__device__ __forceinline__ void mma_tf32(float* c, const uint32_t* a, const uint32_t* b) {
    asm volatile(
        "mma.sync.aligned.m16n8k8.row.col.f32.tf32.tf32.f32 "
        "{%0,%1,%2,%3},{%4,%5,%6,%7},{%8,%9},{%0,%1,%2,%3};"
        : "+f"(c[0]), "+f"(c[1]), "+f"(c[2]), "+f"(c[3])
        : "r"(a[0]), "r"(a[1]), "r"(a[2]), "r"(a[3]), "r"(b[0]), "r"(b[1]));
}

// vectorized tf32 pre-rounding: dst[i] = tf32(src[i]); n % 4 == 0
__global__ __launch_bounds__(256) void cvt_tf(const float* __restrict__ src,
                                              float* __restrict__ dst, int n)
{
    int i = (blockIdx.x*256 + threadIdx.x) * 4;
    if (i < n) {
        float4 v = *(const float4*)(src + i);
        v.x = f2tf_f(v.x); v.y = f2tf_f(v.y); v.z = f2tf_f(v.z); v.w = f2tf_f(v.w);
        *(float4*)(dst + i) = v;
    }
}

// pack Wq|Wk|Wv into [L][768][2304], tf32-rounded
__global__ __launch_bounds__(256) void pack_qkv(
    const float* __restrict__ Wq, const float* __restrict__ Wk,
    const float* __restrict__ Wv, float* __restrict__ dst)
{
    int idx = blockIdx.x*256 + threadIdx.x;
    if (idx >= NLAYER*DMODEL*NQKV) return;
    int l = idx / (DMODEL*NQKV);
    int r = idx % (DMODEL*NQKV);
    int k = r / NQKV, n = r % NQKV;
    float s;
    size_t base = ((size_t)l*DMODEL + k)*DMODEL;
    if (n < DMODEL)           s = Wq[base + n];
    else if (n < 2*DMODEL)    s = Wk[base + n - DMODEL];
    else                      s = Wv[base + n - 2*DMODEL];
    dst[idx] = f2tf_f(s);
}

__global__ __launch_bounds__(256) void pack_bias(
    const float* __restrict__ bq, const float* __restrict__ bk,
    const float* __restrict__ bv, float* __restrict__ dst)
{
    int idx = blockIdx.x*256 + threadIdx.x;
    if (idx >= NLAYER*NQKV) return;
    int l = idx / NQKV, n = idx % NQKV;
    float s;
    if (n < DMODEL)           s = bq[l*DMODEL + n];
    else if (n < 2*DMODEL)    s = bk[l*DMODEL + n - DMODEL];
    else                      s = bv[l*DMODEL + n - 2*DMODEL];
    dst[idx] = s;
}

// ---------------- reductions ----------------
__device__ __forceinline__ float blockSum(float v, float* red) {
    __syncthreads();
    #pragma unroll
    for (int o = 16; o; o >>= 1) v += __shfl_down_sync(0xffffffffu, v, o);
    if ((threadIdx.x & 31) == 0) red[threadIdx.x >> 5] = v;
    __syncthreads();
    float r = (threadIdx.x < 8) ? red[threadIdx.x] : 0.f;
    if (threadIdx.x < 32) {
        #pragma unroll
        for (int o = 16; o; o >>= 1) r += __shfl_down_sync(0xffffffffu, r, o);
    }
    if (threadIdx.x == 0) red[0] = r;
    __syncthreads();
    return red[0];
}

// ---------------- embedding + layernorm (writes x and tf32 copy) ----------------
__global__ __launch_bounds__(256) void embed_ln(
    const int* __restrict__ ids, const float* __restrict__ etok,
    const float* __restrict__ epos, const float* __restrict__ g,
    const float* __restrict__ bi, float* __restrict__ x, float* __restrict__ xtf)
{
    __shared__ float red[8];
    int t = blockIdx.x;
    int s = t & (SEQ - 1);
    int tid = threadIdx.x;
    int id = ids[t];
    float e[3]; float sum = 0.f;
    #pragma unroll
    for (int i = 0; i < 3; i++) {
        int d = tid + i*256;
        e[i] = etok[(size_t)id*DMODEL + d] + epos[(size_t)s*DMODEL + d];
        sum += e[i];
    }
    float mean = blockSum(sum, red) * (1.f/DMODEL);
    float vs = 0.f;
    #pragma unroll
    for (int i = 0; i < 3; i++) { float df = e[i]-mean; vs += df*df; }
    float var = blockSum(vs, red) * (1.f/DMODEL);
    float inv = rsqrtf(var + 1e-12f);
    #pragma unroll
    for (int i = 0; i < 3; i++) {
        int d = tid + i*256;
        float o = (e[i]-mean)*inv*g[d] + bi[d];
        x  [(size_t)t*DMODEL + d] = o;
        xtf[(size_t)t*DMODEL + d] = f2tf_f(o);
    }
}

// ---------------- residual add + layernorm (in-place on x, tf32 copy out) ----------------
__global__ __launch_bounds__(256) void add_ln(
    float* __restrict__ x, const float* __restrict__ y,
    const float* __restrict__ g, const float* __restrict__ bi,
    float* __restrict__ xtf)
{
    __shared__ float red[8];
    int t = blockIdx.x;
    int tid = threadIdx.x;
    float e[3]; float sum = 0.f;
    #pragma unroll
    for (int i = 0; i < 3; i++) {
        int d = tid + i*256;
        e[i] = x[(size_t)t*DMODEL + d] + y[(size_t)t*DMODEL + d];
        sum += e[i];
    }
    float mean = blockSum(sum, red) * (1.f/DMODEL);
    float vs = 0.f;
    #pragma unroll
    for (int i = 0; i < 3; i++) { float df = e[i]-mean; vs += df*df; }
    float var = blockSum(vs, red) * (1.f/DMODEL);
    float inv = rsqrtf(var + 1e-12f);
    #pragma unroll
    for (int i = 0; i < 3; i++) {
        int d = tid + i*256;
        float o = (e[i]-mean)*inv*g[d] + bi[d];
        x  [(size_t)t*DMODEL + d] = o;
        xtf[(size_t)t*DMODEL + d] = f2tf_f(o);
    }
}

// ---------------- tf32 tensor-core GEMM, 3-stage pipeline ----------------
// C[M,N] = A[M,K] @ B[K,N] + bias; act: GELU; cvtout: round result to tf32.
// BM=BN=128, BK=32, 256 threads. Warp grid 2(M)x4(N), warp tile 64x32 = 4x4 m16n8k8.
#define A_PAD 36
#define B_PAD 136
#define STG_FLT (128*A_PAD + 32*B_PAD)
#define GEMM_SMEM (3*STG_FLT*4)

__global__ __launch_bounds__(256, 2) void gemm_tf32(
    const float* __restrict__ A, const float* __restrict__ B,
    const float* __restrict__ bias, float* __restrict__ C,
    int M, int N, int K, int act, int cvtout)
{
    extern __shared__ float sm[];

    const int tid  = threadIdx.x;
    const int warp = tid >> 5, lane = tid & 31;
    const int g = lane >> 2, t = lane & 3;     // groupID, threadID-in-group
    const int wm = warp >> 2;                  // 0..1
    const int wn = warp & 3;                   // 0..3
    const int bm = blockIdx.y << 7;
    const int bn = blockIdx.x << 7;

    float acc[4][4][4] = {};

    auto load_stage = [&](int stg, int k0) {
        float* Ad = sm + stg*STG_FLT;
        float* Bd = Ad + 128*A_PAD;
        #pragma unroll
        for (int i = 0; i < 4; i++) {
            int f = tid + i*256;
            int r = f >> 3, c = (f & 7) << 2;
            cpa16(Ad + r*A_PAD + c, A + (size_t)(bm+r)*K + k0 + c);
            int br = f >> 5, bc = (f & 31) << 2;
            cpa16(Bd + br*B_PAD + bc, B + (size_t)(k0+br)*N + bn + bc);
        }
        asm volatile("cp.async.commit_group;" ::: "memory");
    };

    const int nk = K >> 5;
    load_stage(0, 0);
    load_stage(1, 32);

    for (int it = 0; it < nk; it++) {
        int s = it - (it >= 3 ? (it/3)*3 : 0);  // it % 3
        s = it % 3;
        if (it + 1 < nk) { asm volatile("cp.async.wait_group 1;" ::: "memory"); }
        else             { asm volatile("cp.async.wait_group 0;" ::: "memory"); }
        __syncthreads();
        if (it + 2 < nk) load_stage((it+2)%3, (it+2) << 5);

        const float* Ac = sm + s*STG_FLT;
        const float* Bc = Ac + 128*A_PAD;
        #pragma unroll
        for (int ks = 0; ks < 4; ks++) {
            const int kb = ks*8;
            uint32_t af[4][4], bf[4][2];
            #pragma unroll
            for (int mt = 0; mt < 4; mt++) {
                int m = wm*64 + mt*16 + g;
                af[mt][0] = __float_as_uint(Ac[(m  )*A_PAD + kb + t    ]);
                af[mt][1] = __float_as_uint(Ac[(m+8)*A_PAD + kb + t    ]);
                af[mt][2] = __float_as_uint(Ac[(m  )*A_PAD + kb + t + 4]);
                af[mt][3] = __float_as_uint(Ac[(m+8)*A_PAD + kb + t + 4]);
            }
            #pragma unroll
            for (int nt = 0; nt < 4; nt++) {
                int n = wn*32 + nt*8 + g;
                bf[nt][0] = __float_as_uint(Bc[(kb + t    )*B_PAD + n]);
                bf[nt][1] = __float_as_uint(Bc[(kb + t + 4)*B_PAD + n]);
            }
            #pragma unroll
            for (int mt = 0; mt < 4; mt++)
                #pragma unroll
                for (int nt = 0; nt < 4; nt++)
                    mma_tf32(acc[mt][nt], af[mt], bf[nt]);
        }
    }

    // epilogue
    #pragma unroll
    for (int mt = 0; mt < 4; mt++) {
        #pragma unroll
        for (int nt = 0; nt < 4; nt++) {
            int row = bm + wm*64 + mt*16 + g;
            int col = bn + wn*32 + nt*8 + t*2;
            float b0 = bias[col], b1 = bias[col+1];
            #pragma unroll
            for (int h = 0; h < 2; h++) {       // h=0: rows g, h=1: rows g+8
                float u0 = acc[mt][nt][2*h+0] + b0;
                float u1 = acc[mt][nt][2*h+1] + b1;
                if (act) {
                    u0 = 0.5f*u0*(1.f + tanhf(0.7978845608028654f*(u0 + 0.044715f*u0*u0*u0)));
                    u1 = 0.5f*u1*(1.f + tanhf(0.7978845608028654f*(u1 + 0.044715f*u1*u1*u1)));
                }
                if (cvtout) { u0 = f2tf_f(u0); u1 = f2tf_f(u1); }
                float2 p = make_float2(u0, u1);
                *(float2*)(C + (size_t)(row + 8*h)*N + col) = p;
            }
        }
    }
}

// ---------------- flash attention core (shared by sparse + full-split) ----------------
// smem: Qt[64*68] + Kt[64*68] + Vs[64*68] + Ps[64*68] = 69632 B
#define SPARSE_SMEM (4*64*68*4)

// Computes flash over 8 key blocks given by idx[]; returns unnormalized o + (m,l).
// q/k/v pointers have row stride `str`.
__device__ __forceinline__ void flash8(
    const float* q, const float* k, const float* v, int str,
    int b, int h, int qb, const int* idx,
    float* sm, float o[4][4], float m_run[4], float l_run[4])
{
    float* Qt = sm;                 // [d][qr] stride 68
    float* Kt = sm + 64*68;         // [d][kc] stride 68
    float* Vs = sm + 2*64*68;       // [kc][d] stride 68
    float* Ps = sm + 3*64*68;       // [qr][kc] stride 68
    const int tid = threadIdx.x;
    const int tr = tid >> 4, tc = tid & 15;
    const float scale = 0.125f;

    const float* qbase = q + ((size_t)(b*SEQ + qb*64))*str + h*DHEAD;
    for (int e = tid; e < 64*64; e += 256) {
        int r = e >> 6, d = e & 63;
        Qt[d*68 + r] = qbase[(size_t)r*str + d];
    }

    #pragma unroll
    for (int i = 0; i < 4; i++) {
        m_run[i] = -1e30f; l_run[i] = 0.f;
        #pragma unroll
        for (int j = 0; j < 4; j++) o[i][j] = 0.f;
    }

    for (int kb = 0; kb < 8; kb++) {
        const float* kbase = k + ((size_t)(b*SEQ + idx[kb]*64))*str + h*DHEAD;
        const float* vbase = v + ((size_t)(b*SEQ + idx[kb]*64))*str + h*DHEAD;
        __syncthreads();
        for (int e = tid; e < 64*64; e += 256) {
            int r = e >> 6, d = e & 63;
            Kt[d*68 + r] = kbase[(size_t)r*str + d];
            Vs[r*68 + d] = vbase[(size_t)r*str + d];
        }
        __syncthreads();
        float s[4][4] = {};
        #pragma unroll 8
        for (int d = 0; d < 64; d++) {
            float a[4], bb[4];
            #pragma unroll
            for (int i = 0; i < 4; i++) a[i] = Qt[d*68 + tr*4 + i];
            #pragma unroll
            for (int j = 0; j < 4; j++) bb[j] = Kt[d*68 + tc*4 + j];
            #pragma unroll
            for (int i = 0; i < 4; i++)
                #pragma unroll
                for (int j = 0; j < 4; j++)
                    s[i][j] = fmaf(a[i], bb[j], s[i][j]);
        }
        #pragma unroll
        for (int i = 0; i < 4; i++) {
            float rm = -1e30f;
            #pragma unroll
            for (int j = 0; j < 4; j++) { s[i][j] *= scale; rm = fmaxf(rm, s[i][j]); }
            rm = fmaxf(rm, __shfl_xor_sync(0xffffffffu, rm, 1));
            rm = fmaxf(rm, __shfl_xor_sync(0xffffffffu, rm, 2));
            rm = fmaxf(rm, __shfl_xor_sync(0xffffffffu, rm, 4));
            rm = fmaxf(rm, __shfl_xor_sync(0xffffffffu, rm, 8));
            float mnew = fmaxf(m_run[i], rm);
            float fac = __expf(m_run[i] - mnew);
            float ps = 0.f;
            #pragma unroll
            for (int j = 0; j < 4; j++) {
                float p = __expf(s[i][j] - mnew);
                Ps[(tr*4+i)*68 + tc*4 + j] = p;
                ps += p;
            }
            ps += __shfl_xor_sync(0xffffffffu, ps, 1);
            ps += __shfl_xor_sync(0xffffffffu, ps, 2);
            ps += __shfl_xor_sync(0xffffffffu, ps, 4);
            ps += __shfl_xor_sync(0xffffffffu, ps, 8);
            l_run[i] = l_run[i]*fac + ps;
            m_run[i] = mnew;
            #pragma unroll
            for (int j = 0; j < 4; j++) o[i][j] *= fac;
        }
        __syncthreads();
        #pragma unroll 8
        for (int kk = 0; kk < 64; kk++) {
            float p[4], vv[4];
            #pragma unroll
            for (int i = 0; i < 4; i++) p[i] = Ps[(tr*4+i)*68 + kk];
            #pragma unroll
            for (int j = 0; j < 4; j++) vv[j] = Vs[kk*68 + tc*4 + j];
            #pragma unroll
            for (int i = 0; i < 4; i++)
                #pragma unroll
                for (int j = 0; j < 4; j++)
                    o[i][j] = fmaf(p[i], vv[j], o[i][j]);
        }
    }
}

// sparse block attention: query blocks 1..62, grid (62, H, B)
__global__ __launch_bounds__(256, 2) void sparse_attn(
    const float* __restrict__ q, const float* __restrict__ k,
    const float* __restrict__ v, int str, const int* __restrict__ rnd,
    float* __restrict__ out)
{
    extern __shared__ float sm[];
    const int qb = blockIdx.x + 1;
    const int h = blockIdx.y, b = blockIdx.z;
    const int tid = threadIdx.x;
    const int tr = tid >> 4, tc = tid & 15;

    int idx[8];
    idx[0] = 0; idx[1] = qb-1; idx[2] = qb; idx[3] = qb+1; idx[4] = NBLK-1;
    #pragma unroll
    for (int j = 0; j < RRAND; j++)
        idx[5+j] = rnd[((size_t)h*NBLK + qb)*RRAND + j];

    float o[4][4], m_run[4], l_run[4];
    flash8(q, k, v, str, b, h, qb, idx, sm, o, m_run, l_run);

    float* obase = out + ((size_t)(b*SEQ + qb*64))*DMODEL + h*DHEAD;
    #pragma unroll
    for (int i = 0; i < 4; i++) {
        float inv = 1.f / l_run[i];
        #pragma unroll
        for (int j = 0; j < 4; j++)
            obase[(size_t)(tr*4+i)*DMODEL + tc*4 + j] = f2tf_f(o[i][j] * inv);
    }
}

// full-attention partials: grid (8 splits, 2 rbi, B*H). Each CTA: 8 key blocks.
// partial layout per (bh,rbi,split): [64*64 o | 64 m | 64 l] = 4224 floats
__global__ __launch_bounds__(256, 2) void fa_part(
    const float* __restrict__ q, const float* __restrict__ k,
    const float* __restrict__ v, int str, float* __restrict__ fs)
{
    extern __shared__ float sm[];
    const int split = blockIdx.x, rbi = blockIdx.y, bh = blockIdx.z;
    const int b = bh / HEADS, h = bh % HEADS;
    const int qb = rbi ? (NBLK-1) : 0;
    const int tid = threadIdx.x;
    const int tr = tid >> 4, tc = tid & 15;

    int idx[8];
    #pragma unroll
    for (int j = 0; j < 8; j++) idx[j] = split*8 + j;

    float o[4][4], m_run[4], l_run[4];
    flash8(q, k, v, str, b, h, qb, idx, sm, o, m_run, l_run);

    float* pb = fs + ((size_t)((bh*2 + rbi)*8 + split)) * 4224;
    #pragma unroll
    for (int i = 0; i < 4; i++) {
        #pragma unroll
        for (int j = 0; j < 4; j++)
            pb[(tr*4+i)*64 + tc*4 + j] = o[i][j];
        if (tc == 0) {
            pb[4096 + tr*4 + i] = m_run[i];
            pb[4160 + tr*4 + i] = l_run[i];
        }
    }
}

// combine 8 partials: grid (2, B*H), 256 threads (4 threads per row, 16 cols each)
__global__ __launch_bounds__(256) void fa_reduce(
    const float* __restrict__ fs, float* __restrict__ out)
{
    const int rbi = blockIdx.x, bh = blockIdx.y;
    const int b = bh / HEADS, h = bh % HEADS;
    const int qb = rbi ? (NBLK-1) : 0;
    const int tid = threadIdx.x;
    const int row = tid >> 2, cg = (tid & 3) * 16;
    const float* base = fs + ((size_t)(bh*2 + rbi)*8) * 4224;

    float pm[8], pl[8], M = -1e30f;
    #pragma unroll
    for (int s = 0; s < 8; s++) {
        pm[s] = base[s*4224 + 4096 + row];
        pl[s] = base[s*4224 + 4160 + row];
        M = fmaxf(M, pm[s]);
    }
    float f[8], L = 0.f;
    #pragma unroll
    for (int s = 0; s < 8; s++) { f[s] = __expf(pm[s] - M); L += pl[s]*f[s]; }
    float invL = 1.f / L;

    float* obase = out + ((size_t)(b*SEQ + qb*64 + row))*DMODEL + h*DHEAD;
    #pragma unroll
    for (int c = 0; c < 16; c++) {
        float o = 0.f;
        #pragma unroll
        for (int s = 0; s < 8; s++)
            o += base[s*4224 + row*64 + cg + c] * f[s];
        obase[cg + c] = f2tf_f(o * invL);
    }
}

// ---------------- mean pool + fc ----------------
__global__ __launch_bounds__(256) void pool1(const float* __restrict__ x, float* __restrict__ part)
{
    int c = blockIdx.x, b = blockIdx.y;
    int tid = threadIdx.x;
    #pragma unroll
    for (int i = 0; i < 3; i++) {
        int d = tid + i*256;
        const float* base = x + ((size_t)(b*SEQ + c*64))*DMODEL + d;
        float s = 0.f;
        #pragma unroll 8
        for (int t = 0; t < 64; t++) s += base[(size_t)t*DMODEL];
        part[((size_t)(b*64 + c))*DMODEL + d] = s;
    }
}

__global__ __launch_bounds__(256) void pool2(
    const float* __restrict__ part, const float* __restrict__ fcw,
    const float* __restrict__ fcb, float* __restrict__ out)
{
    __shared__ float red[8];
    int b = blockIdx.x, tid = threadIdx.x;
    float accv = 0.f;
    #pragma unroll
    for (int i = 0; i < 3; i++) {
        int d = tid + i*256;
        float s = 0.f;
        for (int c = 0; c < 64; c++) s += part[((size_t)(b*64 + c))*DMODEL + d];
        accv += (s * (1.f/SEQ)) * fcw[d];
    }
    float tot = blockSum(accv, red);
    if (tid == 0) out[b] = tot + fcb[0];
}

// ---------------- launch ----------------
extern "C" void kernel_launch(void* const* d_in, const int* in_sizes, int n_in,
                              void* d_out, int out_size)
{
    const int*   ids   = (const int*)  d_in[0];
    const int*   rnd   = (const int*)  d_in[1];
    const float* etok  = (const float*)d_in[2];
    const float* epos  = (const float*)d_in[3];
    const float* lng   = (const float*)d_in[4];
    const float* lnb   = (const float*)d_in[5];
    const float* Wq    = (const float*)d_in[6];
    const float* bq    = (const float*)d_in[7];
    const float* Wk    = (const float*)d_in[8];
    const float* bk    = (const float*)d_in[9];
    const float* Wv    = (const float*)d_in[10];
    const float* bv    = (const float*)d_in[11];
    const float* Wo    = (const float*)d_in[12];
    const float* bo    = (const float*)d_in[13];
    const float* ln1g  = (const float*)d_in[14];
    const float* ln1b  = (const float*)d_in[15];
    const float* W1    = (const float*)d_in[16];
    const float* b1    = (const float*)d_in[17];
    const float* W2    = (const float*)d_in[18];
    const float* b2    = (const float*)d_in[19];
    const float* ln2g  = (const float*)d_in[20];
    const float* ln2b  = (const float*)d_in[21];
    const float* fcw   = (const float*)d_in[22];
    const float* fcb   = (const float*)d_in[23];
    float* out = (float*)d_out;

    float *x, *xtf, *ao, *t, *h, *fs, *wtf, *bqkv;
    cudaGetSymbolAddress((void**)&x,    g_x);
    cudaGetSymbolAddress((void**)&xtf,  g_xtf);
    cudaGetSymbolAddress((void**)&ao,   g_ao);
    cudaGetSymbolAddress((void**)&t,    g_t);
    cudaGetSymbolAddress((void**)&h,    g_h);
    cudaGetSymbolAddress((void**)&fs,   g_fs);
    cudaGetSymbolAddress((void**)&wtf,  g_wtf);
    cudaGetSymbolAddress((void**)&bqkv, g_bqkv);

    cudaFuncSetAttribute(sparse_attn, cudaFuncAttributeMaxDynamicSharedMemorySize, SPARSE_SMEM);
    cudaFuncSetAttribute(fa_part,     cudaFuncAttributeMaxDynamicSharedMemorySize, SPARSE_SMEM);
    cudaFuncSetAttribute(gemm_tf32,   cudaFuncAttributeMaxDynamicSharedMemorySize, GEMM_SMEM);

    // ---- pre-round / pack weights (once per call) ----
    const int NSQ = NLAYER*DMODEL*DMODEL;
    const int NFF = NLAYER*DMODEL*DFF;
    pack_qkv<<<(NLAYER*DMODEL*NQKV + 255)/256, 256>>>(Wq, Wk, Wv, wtf + WOFF_QKV);
    pack_bias<<<(NLAYER*NQKV + 255)/256, 256>>>(bq, bk, bv, bqkv);
    cvt_tf<<<NSQ/1024, 256>>>(Wo, wtf + WOFF_O, NSQ);
    cvt_tf<<<NFF/1024, 256>>>(W1, wtf + WOFF_1, NFF);
    cvt_tf<<<NFF/1024, 256>>>(W2, wtf + WOFF_2, NFF);

    embed_ln<<<TOK, 256>>>(ids, etok, epos, lng, lnb, x, xtf);

    for (int l = 0; l < NLAYER; l++) {
        const float* Wqkvl = wtf + WOFF_QKV + (size_t)l*DMODEL*NQKV;
        const float* Wol   = wtf + WOFF_O   + (size_t)l*DMODEL*DMODEL;
        const float* W1l   = wtf + WOFF_1   + (size_t)l*DMODEL*DFF;
        const float* W2l   = wtf + WOFF_2   + (size_t)l*DFF*DMODEL;

        // fused QKV: output in g_h (row stride 2304)
        gemm_tf32<<<dim3(NQKV/128, TOK/128), 256, GEMM_SMEM>>>(
            xtf, Wqkvl, bqkv + l*NQKV, h, TOK, NQKV, DMODEL, 0, 0);

        const float* q = h, *k = h + DMODEL, *v = h + 2*DMODEL;
        sparse_attn<<<dim3(NBLK-2, HEADS, BATCH), 256, SPARSE_SMEM>>>(q, k, v, NQKV, rnd, ao);
        fa_part<<<dim3(8, 2, BATCH*HEADS), 256, SPARSE_SMEM>>>(q, k, v, NQKV, fs);
        fa_reduce<<<dim3(2, BATCH*HEADS), 256>>>(fs, ao);

        gemm_tf32<<<dim3(DMODEL/128, TOK/128), 256, GEMM_SMEM>>>(
            ao, Wol, bo + l*DMODEL, t, TOK, DMODEL, DMODEL, 0, 0);
        add_ln<<<TOK, 256>>>(x, t, ln1g + l*DMODEL, ln1b + l*DMODEL, xtf);

        gemm_tf32<<<dim3(DFF/128, TOK/128), 256, GEMM_SMEM>>>(
            xtf, W1l, b1 + l*DFF, h, TOK, DFF, DMODEL, 1, 1);
        gemm_tf32<<<dim3(DMODEL/128, TOK/128), 256, GEMM_SMEM>>>(
            h, W2l, b2 + l*DMODEL, t, TOK, DMODEL, DFF, 0, 0);
        add_ln<<<TOK, 256>>>(x, t, ln2g + l*DMODEL, ln2b + l*DMODEL, xtf);
    }

    pool1<<<dim3(64, BATCH), 256>>>(x, fs);
    pool2<<<BATCH, 256>>>(fs, fcw, fcb, out);
}